// round 6
// baseline (speedup 1.0000x reference)
#include <cuda_runtime.h>
#include <cuda_fp16.h>
#include <math.h>
#include <stdint.h>

// Problem constants
#define BB 2
#define SS 2048
#define DD 1024
#define HH 16
#define DQ 64

// Attention tiling
#define BM 64
#define BN 64

// ctx scratch, split fp16 hi/lo
__device__ __half g_ctx_h[BB * SS * DD];
__device__ __half g_ctx_l[BB * SS * DD];
// W hi fp16 (lo not needed: proj is 2-term)
__device__ __half g_w_h[DD * DD];
__device__ __half g_w_l[DD * DD];

// ===========================================================================
// Helpers
// ===========================================================================
__device__ __forceinline__ uint32_t smem_u32(const void* p) {
    uint32_t a;
    asm("{ .reg .u64 t; cvta.to.shared.u64 t, %1; cvt.u32.u64 %0, t; }" : "=r"(a) : "l"(p));
    return a;
}
__device__ __forceinline__ uint32_t swz(uint32_t off) {
    return off ^ ((off >> 3) & 0x70);
}
__device__ __forceinline__ void ldsm4(uint32_t* r, uint32_t addr) {
    asm volatile("ldmatrix.sync.aligned.m8n8.x4.shared.b16 {%0,%1,%2,%3}, [%4];"
                 : "=r"(r[0]), "=r"(r[1]), "=r"(r[2]), "=r"(r[3]) : "r"(addr));
}
__device__ __forceinline__ void ldsm4t(uint32_t* r, uint32_t addr) {
    asm volatile("ldmatrix.sync.aligned.m8n8.x4.trans.shared.b16 {%0,%1,%2,%3}, [%4];"
                 : "=r"(r[0]), "=r"(r[1]), "=r"(r[2]), "=r"(r[3]) : "r"(addr));
}
// fp16 HMMA: D += A(16x16) * B(16x8), f32 accum
__device__ __forceinline__ void mma16816(float* c, const uint32_t* a, uint32_t b0, uint32_t b1) {
    asm volatile("mma.sync.aligned.m16n8k16.row.col.f32.f16.f16.f32 "
                 "{%0,%1,%2,%3}, {%4,%5,%6,%7}, {%8,%9}, {%0,%1,%2,%3};"
                 : "+f"(c[0]), "+f"(c[1]), "+f"(c[2]), "+f"(c[3])
                 : "r"(a[0]), "r"(a[1]), "r"(a[2]), "r"(a[3]), "r"(b0), "r"(b1));
}
// fp16 hi/lo split of a float pair
__device__ __forceinline__ void split2h(float x, float y, uint32_t& hi, uint32_t& lo) {
    __half2 h = __floats2half2_rn(x, y);
    float rx = x - __low2float(h);
    float ry = y - __high2float(h);
    __half2 l = __floats2half2_rn(rx, ry);
    hi = *reinterpret_cast<uint32_t*>(&h);
    lo = *reinterpret_cast<uint32_t*>(&l);
}
__device__ __forceinline__ void split4h(float4 v, uint2& hi, uint2& lo) {
    split2h(v.x, v.y, hi.x, lo.x);
    split2h(v.z, v.w, hi.y, lo.y);
}
__device__ __forceinline__ uint32_t pack2h(float x, float y) {
    __half2 h = __floats2half2_rn(x, y);
    return *reinterpret_cast<uint32_t*>(&h);
}
__device__ __forceinline__ void cpa16(uint32_t d, const void* s) {
    asm volatile("cp.async.cg.shared.global [%0], [%1], 16;" :: "r"(d), "l"(s));
}
#define CP_COMMIT() asm volatile("cp.async.commit_group;" ::: "memory")
#define CP_WAIT1()  asm volatile("cp.async.wait_group 1;" ::: "memory")

// ===========================================================================
// W pre-split: f32 -> fp16 hi (+lo, cheap; lo kept for safety/debug use)
// ===========================================================================
extern "C" __global__ void __launch_bounds__(256)
convert_w(const float* __restrict__ W)
{
    int i = blockIdx.x * 256 + threadIdx.x;
    float4 v = reinterpret_cast<const float4*>(W)[i];
    uint2 hi, lo;
    split4h(v, hi, lo);
    reinterpret_cast<uint2*>(g_w_h)[i] = hi;
}

// ===========================================================================
// Row-0 fix: reference row q=0 is fully masked -> uniform softmax over ALL
// 2048 keys -> ctx = mean_s V. Computed here; overwrites attn's row-0 output.
// Grid (HH, BB), 256 threads (64 d x 4 s-chunks).
// ===========================================================================
extern "C" __global__ void __launch_bounds__(256)
meanv_fix(const float* __restrict__ V)
{
    __shared__ float red[256];
    const int h = blockIdx.x, b = blockIdx.y;
    const int t = threadIdx.x;
    const int d = t & 63;
    const int sc = t >> 6;
    const float* src = V + (size_t)b * SS * DD + h * DQ + d;
    float s = 0.0f;
#pragma unroll 8
    for (int i = sc * 512; i < sc * 512 + 512; i++)
        s += src[(size_t)i * DD];
    red[t] = s;
    __syncthreads();
    if (t < 64) {
        float m = (red[t] + red[t + 64] + red[t + 128] + red[t + 192]) * (1.0f / 2048.0f);
        size_t idx = (size_t)b * SS * DD + h * DQ + d;
        __half hh = __float2half_rn(m);
        g_ctx_h[idx] = hh;
        g_ctx_l[idx] = __float2half_rn(m - __half2float(hh));
    }
}

// ===========================================================================
// Attention smem layout (fp16 tiles, 8 KB each)
// ===========================================================================
#define SM_QH 0
#define SM_QL 8192
#define SM_KH 16384
#define SM_KL 24576
#define SM_VH 32768
#define SM_VL 40960
#define SMEM_BYTES 49152

// ===========================================================================
// Flash attention: fp16 HMMA. QK = 3-term hi/lo split, PV = 2 mmas
// (single-fp16 P x {V_hi, V_lo}). Masked p = 0 exactly (matches reference).
// 128 threads (4 warps x 16 query rows). Grid (32, 16, 2).
// ===========================================================================
extern "C" __global__ void __launch_bounds__(128)
attn_mma(const float* __restrict__ Q,
         const float* __restrict__ K,
         const float* __restrict__ V)
{
    extern __shared__ char smc[];
    const uint32_t sb = smem_u32(smc);
    const int tid  = threadIdx.x;
    const int lane = tid & 31;
    const int wid  = tid >> 5;

    // Work-descending qt order; qt0 (1 tile) last.
    const int bx = blockIdx.x;
    const int qt = (bx == 31) ? 0 : (31 - bx);
    const int h  = blockIdx.y;
    const int b  = blockIdx.z;
    const int q0 = qt * BM;

    const float* Qb = Q + ((size_t)(b * SS + q0)) * DD + h * DQ;
    const float* Kb = K + ((size_t)b * SS) * DD + h * DQ;
    const float* Vb = V + ((size_t)b * SS) * DD + h * DQ;

#pragma unroll
    for (int it = 0; it < 8; it++) {
        int idx = it * 128 + tid;
        int r = idx >> 4;
        int g = idx & 15;
        float4 q4 = *reinterpret_cast<const float4*>(Qb + (size_t)r * DD + g * 4);
        uint2 hi, lo;
        split4h(q4, hi, lo);
        uint32_t off = swz((uint32_t)(r * 128 + g * 8));
        *reinterpret_cast<uint2*>(smc + SM_QH + off) = hi;
        *reinterpret_cast<uint2*>(smc + SM_QL + off) = lo;
    }

    float Oa[32];
    float l0 = 0.0f, l1 = 0.0f;
#pragma unroll
    for (int i = 0; i < 32; i++) Oa[i] = 0.0f;

    const int nkt = qt + 1;   // qt0: row 0 handled by meanv_fix; rows 1-63 need tile 0 only
    const int qg0 = q0 + wid * 16 + (lane >> 2);
    const int qg1 = qg0 + 8;

    for (int kt = 0; kt < nkt; kt++) {
        const int k0 = kt * BN;
        __syncthreads();

#pragma unroll
        for (int it = 0; it < 8; it++) {
            int idx = it * 128 + tid;
            int r = idx >> 4;
            int g = idx & 15;
            uint32_t off = swz((uint32_t)(r * 128 + g * 8));
            float4 k4 = *reinterpret_cast<const float4*>(Kb + (size_t)(k0 + r) * DD + g * 4);
            uint2 hi, lo;
            split4h(k4, hi, lo);
            *reinterpret_cast<uint2*>(smc + SM_KH + off) = hi;
            *reinterpret_cast<uint2*>(smc + SM_KL + off) = lo;
            float4 v4 = *reinterpret_cast<const float4*>(Vb + (size_t)(k0 + r) * DD + g * 4);
            split4h(v4, hi, lo);
            *reinterpret_cast<uint2*>(smc + SM_VH + off) = hi;
            *reinterpret_cast<uint2*>(smc + SM_VL + off) = lo;
        }
        __syncthreads();

        // ---- S = Q K^T : 3-term fp16 split ----
        float sc[32];
#pragma unroll
        for (int i = 0; i < 32; i++) sc[i] = 0.0f;

#pragma unroll
        for (int kc = 0; kc < 4; kc++) {
            uint32_t ah[4], al[4];
            uint32_t offA = swz((uint32_t)((wid * 16 + (lane & 15)) * 128 +
                                           (kc * 16 + (lane >> 4) * 8) * 2));
            ldsm4(ah, sb + SM_QH + offA);
            ldsm4(al, sb + SM_QL + offA);
#pragma unroll
            for (int nt4 = 0; nt4 < 4; nt4++) {
                uint32_t offB = swz((uint32_t)((nt4 * 16 + (lane & 7) + ((lane >> 4) << 3)) * 128 +
                                               (kc * 16 + ((lane >> 3) & 1) * 8) * 2));
                uint32_t bh[4], bl[4];
                ldsm4(bh, sb + SM_KH + offB);
                ldsm4(bl, sb + SM_KL + offB);
                float* c0 = &sc[nt4 * 8];
                float* c1 = &sc[nt4 * 8 + 4];
                mma16816(c0, ah, bh[0], bh[1]);   // hi*hi
                mma16816(c1, ah, bh[2], bh[3]);
                mma16816(c0, al, bh[0], bh[1]);   // lo*hi
                mma16816(c1, al, bh[2], bh[3]);
                mma16816(c0, ah, bl[0], bl[1]);   // hi*lo
                mma16816(c1, ah, bl[2], bl[3]);
            }
        }

        // ---- softmax: masked -> 0 exactly; pack single-fp16 P ----
        uint32_t pf[16];
#pragma unroll
        for (int nt = 0; nt < 8; nt++) {
            const int kg = k0 + nt * 8 + 2 * (lane & 3);
            float p0 = (kg     >= qg0) ? 0.0f : __expf(sc[nt * 4 + 0] * 0.125f);
            float p1 = (kg + 1 >= qg0) ? 0.0f : __expf(sc[nt * 4 + 1] * 0.125f);
            float p2 = (kg     >= qg1) ? 0.0f : __expf(sc[nt * 4 + 2] * 0.125f);
            float p3 = (kg + 1 >= qg1) ? 0.0f : __expf(sc[nt * 4 + 3] * 0.125f);
            l0 += p0 + p1;
            l1 += p2 + p3;
            pf[nt * 2 + 0] = pack2h(p0, p1);
            pf[nt * 2 + 1] = pack2h(p2, p3);
        }

        // ---- O += P V : 2 mmas per chunk (P x V_hi + P x V_lo) ----
#pragma unroll
        for (int c = 0; c < 4; c++) {
            const uint32_t* pa = &pf[c * 4];
#pragma unroll
            for (int d4 = 0; d4 < 4; d4++) {
                uint32_t offV = swz((uint32_t)((c * 16 + (lane & 7) + ((lane >> 3) & 1) * 8) * 128 +
                                               (d4 * 16 + (lane >> 4) * 8) * 2));
                uint32_t bh[4], bl[4];
                ldsm4t(bh, sb + SM_VH + offV);
                ldsm4t(bl, sb + SM_VL + offV);
                float* o0 = &Oa[d4 * 8];
                float* o1 = &Oa[d4 * 8 + 4];
                mma16816(o0, pa, bh[0], bh[1]);
                mma16816(o1, pa, bh[2], bh[3]);
                mma16816(o0, pa, bl[0], bl[1]);
                mma16816(o1, pa, bl[2], bl[3]);
            }
        }
    }

    // ---- Epilogue ----
    l0 += __shfl_xor_sync(0xffffffffu, l0, 1);
    l0 += __shfl_xor_sync(0xffffffffu, l0, 2);
    l1 += __shfl_xor_sync(0xffffffffu, l1, 1);
    l1 += __shfl_xor_sync(0xffffffffu, l1, 2);
    const float inv0 = (l0 > 0.0f) ? 1.0f / l0 : 0.0f;   // row 0: overwritten by meanv_fix
    const float inv1 = 1.0f / l1;

    const int row0 = q0 + wid * 16 + (lane >> 2);
    const size_t base0 = ((size_t)(b * SS + row0)) * DD + h * DQ;
    const size_t base1 = base0 + (size_t)8 * DD;
#pragma unroll
    for (int nt = 0; nt < 8; nt++) {
        const int col = nt * 8 + 2 * (lane & 3);
        uint32_t hi, lo;
        split2h(Oa[nt * 4 + 0] * inv0, Oa[nt * 4 + 1] * inv0, hi, lo);
        *reinterpret_cast<uint32_t*>(&g_ctx_h[base0 + col]) = hi;
        *reinterpret_cast<uint32_t*>(&g_ctx_l[base0 + col]) = lo;
        split2h(Oa[nt * 4 + 2] * inv1, Oa[nt * 4 + 3] * inv1, hi, lo);
        *reinterpret_cast<uint32_t*>(&g_ctx_h[base1 + col]) = hi;
        *reinterpret_cast<uint32_t*>(&g_ctx_l[base1 + col]) = lo;
    }
}

// ===========================================================================
// Projection v3: 2-term fp16 (ah*bh + al*bh). CTA tile 128x64, BK=64,
// 256 threads (8 warps, warp tile 32x32), cp.async double-buffered.
// A rows: 256 B = [64 h fp16 | 64 l fp16], each half swizzled. B rows: 128 B h.
// Grid (16, 32).
// ===========================================================================
#define PNIT (DD / 64)   // 16 k-iterations

extern "C" __global__ void __launch_bounds__(256, 2)
proj_mma2(const float* __restrict__ bias,
          float* __restrict__ out)
{
    extern __shared__ char psm[];
    // layout: A stage0 [32768], A stage1 [32768], B stage0 [8192], B stage1 [8192]
    char* pA0 = psm;
    char* pA1 = psm + 32768;
    char* pB0 = psm + 65536;
    char* pB1 = psm + 73728;

    const int tid  = threadIdx.x;
    const int lane = tid & 31;
    const int wid  = tid >> 5;
    const int wm   = wid >> 1;
    const int wn   = wid & 1;
    const int j0   = blockIdx.x * 64;
    const int i0   = blockIdx.y * 128;

    const uint32_t sa0 = smem_u32(pA0);
    const uint32_t sa1 = smem_u32(pA1);
    const uint32_t sb0 = smem_u32(pB0);
    const uint32_t sb1 = smem_u32(pB1);

    float acc[32];
#pragma unroll
    for (int i = 0; i < 32; i++) acc[i] = 0.0f;

    auto issue = [&](int stage, int k0) {
        const uint32_t sa = stage ? sa1 : sa0;
        const uint32_t sbm = stage ? sb1 : sb0;
        // A: 128 rows x (8 h + 8 l) 16-B chunks = 2048 chunks
#pragma unroll
        for (int q = 0; q < 8; q++) {
            int id = q * 256 + tid;
            int r = id >> 4;
            int g = id & 15;
            uint32_t dst;
            const __half* src;
            if (g < 8) {
                dst = sa + r * 256 + swz((uint32_t)(g * 16));
                src = &g_ctx_h[(size_t)(i0 + r) * DD + k0 + g * 8];
            } else {
                dst = sa + r * 256 + 128 + swz((uint32_t)((g - 8) * 16));
                src = &g_ctx_l[(size_t)(i0 + r) * DD + k0 + (g - 8) * 8];
            }
            cpa16(dst, src);
        }
        // B: 64 rows x 8 chunks = 512 chunks
#pragma unroll
        for (int q = 0; q < 2; q++) {
            int id = q * 256 + tid;
            int r = id >> 3;
            int g = id & 7;
            cpa16(sbm + r * 128 + swz((uint32_t)(g * 16)),
                  &g_w_h[(size_t)(j0 + r) * DD + k0 + g * 8]);
        }
    };

    issue(0, 0);  CP_COMMIT();
    issue(1, 64); CP_COMMIT();

    for (int it = 0; it < PNIT; it++) {
        CP_WAIT1();
        __syncthreads();
        const uint32_t sa = (it & 1) ? sa1 : sa0;
        const uint32_t sbm = (it & 1) ? sb1 : sb0;

#pragma unroll
        for (int kc = 0; kc < 4; kc++) {
            const int kk = kc * 16;
            uint32_t ah[2][4], al[2][4];
#pragma unroll
            for (int m = 0; m < 2; m++) {
                const uint32_t row = wm * 32 + m * 16 + (lane & 15);
                const uint32_t colb = (kk + (lane >> 4) * 8) * 2;
                ldsm4(ah[m], sa + row * 256 + swz(colb));
                ldsm4(al[m], sa + row * 256 + 128 + swz(colb));
            }
            uint32_t bh[2][4];
#pragma unroll
            for (int nt = 0; nt < 2; nt++) {
                const uint32_t rowb = wn * 32 + nt * 16 + (lane & 7) + ((lane >> 4) << 3);
                const uint32_t colb = (kk + ((lane >> 3) & 1) * 8) * 2;
                ldsm4(bh[nt], sbm + rowb * 128 + swz(colb));
            }
#pragma unroll
            for (int m = 0; m < 2; m++)
#pragma unroll
                for (int nt = 0; nt < 2; nt++) {
                    float* c0 = &acc[(m * 2 + nt) * 8];
                    float* c1 = c0 + 4;
                    mma16816(c0, ah[m], bh[nt][0], bh[nt][1]);   // hi*hi
                    mma16816(c1, ah[m], bh[nt][2], bh[nt][3]);
                    mma16816(c0, al[m], bh[nt][0], bh[nt][1]);   // lo*hi
                    mma16816(c1, al[m], bh[nt][2], bh[nt][3]);
                }
        }

        __syncthreads();
        if (it + 2 < PNIT) {
            issue(it & 1, (it + 2) * 64);
        }
        CP_COMMIT();
    }

    // ---- Epilogue: + bias, f32 out ----
#pragma unroll
    for (int m = 0; m < 2; m++) {
        const int row = i0 + wm * 32 + m * 16 + (lane >> 2);
        float* d0 = out + (size_t)row * DD;
        float* d1 = d0 + (size_t)8 * DD;
#pragma unroll
        for (int nt = 0; nt < 2; nt++) {
#pragma unroll
            for (int n8 = 0; n8 < 2; n8++) {
                const int col = j0 + wn * 32 + nt * 16 + n8 * 8 + 2 * (lane & 3);
                const float* c = &acc[(m * 2 + nt) * 8 + n8 * 4];
                const float b0 = bias[col];
                const float b1 = bias[col + 1];
                *reinterpret_cast<float2*>(d0 + col) = make_float2(c[0] + b0, c[1] + b1);
                *reinterpret_cast<float2*>(d1 + col) = make_float2(c[2] + b0, c[3] + b1);
            }
        }
    }
}

#define PROJ_SMEM 81920

// ===========================================================================
extern "C" void kernel_launch(void* const* d_in, const int* in_sizes, int n_in,
                              void* d_out, int out_size)
{
    const float* Q    = (const float*)d_in[0];
    const float* K    = (const float*)d_in[1];
    const float* V    = (const float*)d_in[2];
    const float* Wo_w = (const float*)d_in[3];
    const float* Wo_b = (const float*)d_in[4];

    convert_w<<<(DD * DD / 4) / 256, 256>>>(Wo_w);

    cudaFuncSetAttribute(attn_mma, cudaFuncAttributeMaxDynamicSharedMemorySize, SMEM_BYTES);
    dim3 agrid(SS / BM, HH, BB);          // (32, 16, 2)
    attn_mma<<<agrid, 128, SMEM_BYTES>>>(Q, K, V);

    dim3 mgrid(HH, BB);
    meanv_fix<<<mgrid, 256>>>(V);

    cudaFuncSetAttribute(proj_mma2, cudaFuncAttributeMaxDynamicSharedMemorySize, PROJ_SMEM);
    dim3 pgrid(DD / 64, (BB * SS) / 128); // (16, 32)
    proj_mma2<<<pgrid, 256, PROJ_SMEM>>>(Wo_b, (float*)d_out);
}

// round 8
// speedup vs baseline: 1.4780x; 1.4780x over previous
#include <cuda_runtime.h>
#include <cuda_fp16.h>
#include <math.h>
#include <stdint.h>

// Problem constants
#define BB 2
#define SS 2048
#define DD 1024
#define HH 16
#define DQ 64

// Attention tiling
#define BM 64
#define BN 64

// ctx scratch, split fp16 hi/lo
__device__ __half g_ctx_h[BB * SS * DD];
__device__ __half g_ctx_l[BB * SS * DD];
// W hi fp16 (proj is 2-term: only hi needed)
__device__ __half g_w_h[DD * DD];
// K/V pre-split fp16 hi/lo
__device__ __half g_k_h[BB * SS * DD];
__device__ __half g_k_l[BB * SS * DD];
__device__ __half g_v_h[BB * SS * DD];
__device__ __half g_v_l[BB * SS * DD];

// ===========================================================================
// Helpers
// ===========================================================================
__device__ __forceinline__ uint32_t smem_u32(const void* p) {
    uint32_t a;
    asm("{ .reg .u64 t; cvta.to.shared.u64 t, %1; cvt.u32.u64 %0, t; }" : "=r"(a) : "l"(p));
    return a;
}
__device__ __forceinline__ uint32_t swz(uint32_t off) {
    return off ^ ((off >> 3) & 0x70);
}
__device__ __forceinline__ void ldsm4(uint32_t* r, uint32_t addr) {
    asm volatile("ldmatrix.sync.aligned.m8n8.x4.shared.b16 {%0,%1,%2,%3}, [%4];"
                 : "=r"(r[0]), "=r"(r[1]), "=r"(r[2]), "=r"(r[3]) : "r"(addr));
}
__device__ __forceinline__ void ldsm4t(uint32_t* r, uint32_t addr) {
    asm volatile("ldmatrix.sync.aligned.m8n8.x4.trans.shared.b16 {%0,%1,%2,%3}, [%4];"
                 : "=r"(r[0]), "=r"(r[1]), "=r"(r[2]), "=r"(r[3]) : "r"(addr));
}
// fp16 HMMA: D += A(16x16) * B(16x8), f32 accum
__device__ __forceinline__ void mma16816(float* c, const uint32_t* a, uint32_t b0, uint32_t b1) {
    asm volatile("mma.sync.aligned.m16n8k16.row.col.f32.f16.f16.f32 "
                 "{%0,%1,%2,%3}, {%4,%5,%6,%7}, {%8,%9}, {%0,%1,%2,%3};"
                 : "+f"(c[0]), "+f"(c[1]), "+f"(c[2]), "+f"(c[3])
                 : "r"(a[0]), "r"(a[1]), "r"(a[2]), "r"(a[3]), "r"(b0), "r"(b1));
}
__device__ __forceinline__ void split2h(float x, float y, uint32_t& hi, uint32_t& lo) {
    __half2 h = __floats2half2_rn(x, y);
    float rx = x - __low2float(h);
    float ry = y - __high2float(h);
    __half2 l = __floats2half2_rn(rx, ry);
    hi = *reinterpret_cast<uint32_t*>(&h);
    lo = *reinterpret_cast<uint32_t*>(&l);
}
__device__ __forceinline__ void split4h(float4 v, uint2& hi, uint2& lo) {
    split2h(v.x, v.y, hi.x, lo.x);
    split2h(v.z, v.w, hi.y, lo.y);
}
__device__ __forceinline__ uint32_t pack2h(float x, float y) {
    __half2 h = __floats2half2_rn(x, y);
    return *reinterpret_cast<uint32_t*>(&h);
}
__device__ __forceinline__ void cpa16(uint32_t d, const void* s) {
    asm volatile("cp.async.cg.shared.global [%0], [%1], 16;" :: "r"(d), "l"(s));
}
#define CP_COMMIT() asm volatile("cp.async.commit_group;" ::: "memory")
#define CP_WAIT0()  asm volatile("cp.async.wait_group 0;" ::: "memory")
#define CP_WAIT1()  asm volatile("cp.async.wait_group 1;" ::: "memory")

// ===========================================================================
// W pre-split (hi only)
// ===========================================================================
extern "C" __global__ void __launch_bounds__(256)
convert_w(const float* __restrict__ W)
{
    int i = blockIdx.x * 256 + threadIdx.x;
    float4 v = reinterpret_cast<const float4*>(W)[i];
    uint2 hi, lo;
    split4h(v, hi, lo);
    reinterpret_cast<uint2*>(g_w_h)[i] = hi;
}

// ===========================================================================
// K/V pre-split: f32 -> fp16 hi/lo. Globals referenced DIRECTLY in device
// code (passing __device__ symbols from host is invalid — R7 bug).
// ===========================================================================
extern "C" __global__ void __launch_bounds__(256)
convert_k(const float* __restrict__ src)
{
    int i0 = (blockIdx.x * 256 + threadIdx.x) * 4;
#pragma unroll
    for (int j = 0; j < 4; j++) {
        float4 v = reinterpret_cast<const float4*>(src)[i0 + j];
        uint2 hi, lo;
        split4h(v, hi, lo);
        reinterpret_cast<uint2*>(g_k_h)[i0 + j] = hi;
        reinterpret_cast<uint2*>(g_k_l)[i0 + j] = lo;
    }
}
extern "C" __global__ void __launch_bounds__(256)
convert_v(const float* __restrict__ src)
{
    int i0 = (blockIdx.x * 256 + threadIdx.x) * 4;
#pragma unroll
    for (int j = 0; j < 4; j++) {
        float4 v = reinterpret_cast<const float4*>(src)[i0 + j];
        uint2 hi, lo;
        split4h(v, hi, lo);
        reinterpret_cast<uint2*>(g_v_h)[i0 + j] = hi;
        reinterpret_cast<uint2*>(g_v_l)[i0 + j] = lo;
    }
}

// ===========================================================================
// Row-0 fix: reference row q=0 fully masked -> uniform softmax -> ctx = mean V.
// ===========================================================================
extern "C" __global__ void __launch_bounds__(256)
meanv_fix(const float* __restrict__ V)
{
    __shared__ float red[256];
    const int h = blockIdx.x, b = blockIdx.y;
    const int t = threadIdx.x;
    const int d = t & 63;
    const int sc = t >> 6;
    const float* src = V + (size_t)b * SS * DD + h * DQ + d;
    float s = 0.0f;
#pragma unroll 8
    for (int i = sc * 512; i < sc * 512 + 512; i++)
        s += src[(size_t)i * DD];
    red[t] = s;
    __syncthreads();
    if (t < 64) {
        float m = (red[t] + red[t + 64] + red[t + 128] + red[t + 192]) * (1.0f / 2048.0f);
        size_t idx = (size_t)b * SS * DD + h * DQ + d;
        __half hh = __float2half_rn(m);
        g_ctx_h[idx] = hh;
        g_ctx_l[idx] = __float2half_rn(m - __half2float(hh));
    }
}

// ===========================================================================
// Attention smem layout (fp16 tiles, 8 KB each; 48 KB total)
// ===========================================================================
#define SM_QH 0
#define SM_QL 8192
#define SM_KH 16384
#define SM_KL 24576
#define SM_VH 32768
#define SM_VL 40960
#define SMEM_BYTES 49152

// ===========================================================================
// Flash attention: fp16 HMMA. QK 3-term, PV 2-term. K/V pre-split -> per-tile
// loads are pure cp.async (no conversion math). 128 threads, grid (32,16,2).
// ===========================================================================
extern "C" __global__ void __launch_bounds__(128)
attn_mma(const float* __restrict__ Q)
{
    extern __shared__ char smc[];
    const uint32_t sb = smem_u32(smc);
    const int tid  = threadIdx.x;
    const int lane = tid & 31;
    const int wid  = tid >> 5;

    const int bx = blockIdx.x;
    const int qt = (bx == 31) ? 0 : (31 - bx);
    const int h  = blockIdx.y;
    const int b  = blockIdx.z;
    const int q0 = qt * BM;

    const float*  Qb  = Q + ((size_t)(b * SS + q0)) * DD + h * DQ;
    const size_t  kvb = (size_t)b * SS * DD + h * DQ;

    // ---- Load Q tile (f32, split in-kernel: read once per CTA) ----
#pragma unroll
    for (int it = 0; it < 8; it++) {
        int idx = it * 128 + tid;
        int r = idx >> 4;
        int g = idx & 15;
        float4 q4 = *reinterpret_cast<const float4*>(Qb + (size_t)r * DD + g * 4);
        uint2 hi, lo;
        split4h(q4, hi, lo);
        uint32_t off = swz((uint32_t)(r * 128 + g * 8));
        *reinterpret_cast<uint2*>(smc + SM_QH + off) = hi;
        *reinterpret_cast<uint2*>(smc + SM_QL + off) = lo;
    }

    float Oa[32];
    float l0 = 0.0f, l1 = 0.0f;
#pragma unroll
    for (int i = 0; i < 32; i++) Oa[i] = 0.0f;

    const int nkt = qt + 1;
    const int qg0 = q0 + wid * 16 + (lane >> 2);
    const int qg1 = qg0 + 8;

    // cp.async chunk coords for K/V tiles (512 chunks per 8-KB tile)
    const int cr = tid >> 1;               // row 0..63
    const int cg = (tid & 1) * 4;          // chunk group 0 or 4

    for (int kt = 0; kt < nkt; kt++) {
        const int k0 = kt * BN;
        __syncthreads();   // previous-iteration smem readers done

        // ---- K/V tiles via cp.async (4 chunks per array per thread) ----
#pragma unroll
        for (int q = 0; q < 4; q++) {
            const int g = cg + q;
            const uint32_t off = swz((uint32_t)(cr * 128 + g * 16));
            const size_t srco = kvb + (size_t)(k0 + cr) * DD + g * 8;
            cpa16(sb + SM_KH + off, &g_k_h[srco]);
            cpa16(sb + SM_KL + off, &g_k_l[srco]);
            cpa16(sb + SM_VH + off, &g_v_h[srco]);
            cpa16(sb + SM_VL + off, &g_v_l[srco]);
        }
        CP_COMMIT();
        CP_WAIT0();
        __syncthreads();

        // ---- S = Q K^T : 3-term fp16 split ----
        float sc[32];
#pragma unroll
        for (int i = 0; i < 32; i++) sc[i] = 0.0f;

#pragma unroll
        for (int kc = 0; kc < 4; kc++) {
            uint32_t ah[4], al[4];
            uint32_t offA = swz((uint32_t)((wid * 16 + (lane & 15)) * 128 +
                                           (kc * 16 + (lane >> 4) * 8) * 2));
            ldsm4(ah, sb + SM_QH + offA);
            ldsm4(al, sb + SM_QL + offA);
#pragma unroll
            for (int nt4 = 0; nt4 < 4; nt4++) {
                uint32_t offB = swz((uint32_t)((nt4 * 16 + (lane & 7) + ((lane >> 4) << 3)) * 128 +
                                               (kc * 16 + ((lane >> 3) & 1) * 8) * 2));
                uint32_t bh[4], bl[4];
                ldsm4(bh, sb + SM_KH + offB);
                ldsm4(bl, sb + SM_KL + offB);
                float* c0 = &sc[nt4 * 8];
                float* c1 = &sc[nt4 * 8 + 4];
                mma16816(c0, ah, bh[0], bh[1]);   // hi*hi
                mma16816(c1, ah, bh[2], bh[3]);
                mma16816(c0, al, bh[0], bh[1]);   // lo*hi
                mma16816(c1, al, bh[2], bh[3]);
                mma16816(c0, ah, bl[0], bl[1]);   // hi*lo
                mma16816(c1, ah, bl[2], bl[3]);
            }
        }

        // ---- softmax: masked -> 0 exactly; single-fp16 P ----
        uint32_t pf[16];
#pragma unroll
        for (int nt = 0; nt < 8; nt++) {
            const int kg = k0 + nt * 8 + 2 * (lane & 3);
            float p0 = (kg     >= qg0) ? 0.0f : __expf(sc[nt * 4 + 0] * 0.125f);
            float p1 = (kg + 1 >= qg0) ? 0.0f : __expf(sc[nt * 4 + 1] * 0.125f);
            float p2 = (kg     >= qg1) ? 0.0f : __expf(sc[nt * 4 + 2] * 0.125f);
            float p3 = (kg + 1 >= qg1) ? 0.0f : __expf(sc[nt * 4 + 3] * 0.125f);
            l0 += p0 + p1;
            l1 += p2 + p3;
            pf[nt * 2 + 0] = pack2h(p0, p1);
            pf[nt * 2 + 1] = pack2h(p2, p3);
        }

        // ---- O += P V : 2-term (P x V_hi + P x V_lo) ----
#pragma unroll
        for (int c = 0; c < 4; c++) {
            const uint32_t* pa = &pf[c * 4];
#pragma unroll
            for (int d4 = 0; d4 < 4; d4++) {
                uint32_t offV = swz((uint32_t)((c * 16 + (lane & 7) + ((lane >> 3) & 1) * 8) * 128 +
                                               (d4 * 16 + (lane >> 4) * 8) * 2));
                uint32_t bh[4], bl[4];
                ldsm4t(bh, sb + SM_VH + offV);
                ldsm4t(bl, sb + SM_VL + offV);
                float* o0 = &Oa[d4 * 8];
                float* o1 = &Oa[d4 * 8 + 4];
                mma16816(o0, pa, bh[0], bh[1]);
                mma16816(o1, pa, bh[2], bh[3]);
                mma16816(o0, pa, bl[0], bl[1]);
                mma16816(o1, pa, bl[2], bl[3]);
            }
        }
    }

    // ---- Epilogue ----
    l0 += __shfl_xor_sync(0xffffffffu, l0, 1);
    l0 += __shfl_xor_sync(0xffffffffu, l0, 2);
    l1 += __shfl_xor_sync(0xffffffffu, l1, 1);
    l1 += __shfl_xor_sync(0xffffffffu, l1, 2);
    const float inv0 = (l0 > 0.0f) ? 1.0f / l0 : 0.0f;   // row 0 overwritten by meanv_fix
    const float inv1 = 1.0f / l1;

    const int row0 = q0 + wid * 16 + (lane >> 2);
    const size_t base0 = ((size_t)(b * SS + row0)) * DD + h * DQ;
    const size_t base1 = base0 + (size_t)8 * DD;
#pragma unroll
    for (int nt = 0; nt < 8; nt++) {
        const int col = nt * 8 + 2 * (lane & 3);
        uint32_t hi, lo;
        split2h(Oa[nt * 4 + 0] * inv0, Oa[nt * 4 + 1] * inv0, hi, lo);
        *reinterpret_cast<uint32_t*>(&g_ctx_h[base0 + col]) = hi;
        *reinterpret_cast<uint32_t*>(&g_ctx_l[base0 + col]) = lo;
        split2h(Oa[nt * 4 + 2] * inv1, Oa[nt * 4 + 3] * inv1, hi, lo);
        *reinterpret_cast<uint32_t*>(&g_ctx_h[base1 + col]) = hi;
        *reinterpret_cast<uint32_t*>(&g_ctx_l[base1 + col]) = lo;
    }
}

// ===========================================================================
// Projection (R5-proven layout, fp16 2-term): out = ctx @ W^T + b.
// CTA 128x64, BK=32, 256 threads (8 warps, 32x32 warp tile), cp.async
// double-buffer. Rows 128 B: A=[32 a_h|32 a_l], B=[32 b_h|unused].
// Grid (16, 32).
// ===========================================================================
#define PNIT (DD / 32)   // 32 k-iterations

extern "C" __global__ void __launch_bounds__(256, 2)
proj_mma2(const float* __restrict__ bias,
          float* __restrict__ out)
{
    __shared__ __align__(16) char sA[2][16384];   // 128 rows x 128 B
    __shared__ __align__(16) char sB[2][8192];    // 64 rows x 128 B

    const int tid  = threadIdx.x;
    const int lane = tid & 31;
    const int wid  = tid >> 5;
    const int wm   = wid >> 1;
    const int wn   = wid & 1;
    const int j0   = blockIdx.x * 64;
    const int i0   = blockIdx.y * 128;

    const uint32_t sa0 = smem_u32(sA[0]);
    const uint32_t sa1 = smem_u32(sA[1]);
    const uint32_t sb0 = smem_u32(sB[0]);
    const uint32_t sb1 = smem_u32(sB[1]);

    float acc[32];
#pragma unroll
    for (int i = 0; i < 32; i++) acc[i] = 0.0f;

    auto issue = [&](int stage, int k0) {
        const uint32_t sa = stage ? sa1 : sa0;
        const uint32_t sbm = stage ? sb1 : sb0;
#pragma unroll
        for (int q = 0; q < 4; q++) {           // A: 1024 chunks (hi+lo)
            int id = q * 256 + tid;
            int r = id >> 3;
            int g = id & 7;
            const __half* src = (g < 4)
                ? &g_ctx_h[(size_t)(i0 + r) * DD + k0 + g * 8]
                : &g_ctx_l[(size_t)(i0 + r) * DD + k0 + (g - 4) * 8];
            cpa16(sa + swz((uint32_t)(r * 128 + g * 16)), src);
        }
        // B: 256 chunks (hi only; lo half of each row left unused)
        {
            int r = tid >> 2;
            int g = tid & 3;
            cpa16(sbm + swz((uint32_t)(r * 128 + g * 16)),
                  &g_w_h[(size_t)(j0 + r) * DD + k0 + g * 8]);
        }
    };

    issue(0, 0);  CP_COMMIT();
    issue(1, 32); CP_COMMIT();

    for (int it = 0; it < PNIT; it++) {
        CP_WAIT1();
        __syncthreads();
        const uint32_t sa = (it & 1) ? sa1 : sa0;
        const uint32_t sbm = (it & 1) ? sb1 : sb0;

#pragma unroll
        for (int kc = 0; kc < 2; kc++) {
            const int kk = kc * 16;
            uint32_t ah[2][4], al[2][4];
#pragma unroll
            for (int m = 0; m < 2; m++) {
                const uint32_t row = wm * 32 + m * 16 + (lane & 15);
                const uint32_t colb = (kk + (lane >> 4) * 8) * 2;
                ldsm4(ah[m], sa + swz(row * 128 + colb));
                ldsm4(al[m], sa + swz(row * 128 + 64 + colb));
            }
            uint32_t bh[2][4];
#pragma unroll
            for (int nt = 0; nt < 2; nt++) {
                const uint32_t rowb = wn * 32 + nt * 16 + (lane & 7) + ((lane >> 4) << 3);
                const uint32_t colb = (kk + ((lane >> 3) & 1) * 8) * 2;
                ldsm4(bh[nt], sbm + swz(rowb * 128 + colb));
            }
#pragma unroll
            for (int m = 0; m < 2; m++)
#pragma unroll
                for (int nt = 0; nt < 2; nt++) {
                    float* c0 = &acc[(m * 2 + nt) * 8];
                    float* c1 = c0 + 4;
                    mma16816(c0, ah[m], bh[nt][0], bh[nt][1]);   // hi*hi
                    mma16816(c1, ah[m], bh[nt][2], bh[nt][3]);
                    mma16816(c0, al[m], bh[nt][0], bh[nt][1]);   // lo*hi
                    mma16816(c1, al[m], bh[nt][2], bh[nt][3]);
                }
        }

        __syncthreads();
        if (it + 2 < PNIT) {
            issue(it & 1, (it + 2) * 32);
        }
        CP_COMMIT();
    }

    // ---- Epilogue: + bias, f32 out ----
#pragma unroll
    for (int m = 0; m < 2; m++) {
        const int row = i0 + wm * 32 + m * 16 + (lane >> 2);
        float* d0 = out + (size_t)row * DD;
        float* d1 = d0 + (size_t)8 * DD;
#pragma unroll
        for (int nt = 0; nt < 2; nt++) {
#pragma unroll
            for (int n8 = 0; n8 < 2; n8++) {
                const int col = j0 + wn * 32 + nt * 16 + n8 * 8 + 2 * (lane & 3);
                const float* c = &acc[(m * 2 + nt) * 8 + n8 * 4];
                const float b0 = bias[col];
                const float b1 = bias[col + 1];
                *reinterpret_cast<float2*>(d0 + col) = make_float2(c[0] + b0, c[1] + b1);
                *reinterpret_cast<float2*>(d1 + col) = make_float2(c[2] + b0, c[3] + b1);
            }
        }
    }
}

// ===========================================================================
extern "C" void kernel_launch(void* const* d_in, const int* in_sizes, int n_in,
                              void* d_out, int out_size)
{
    const float* Q    = (const float*)d_in[0];
    const float* K    = (const float*)d_in[1];
    const float* V    = (const float*)d_in[2];
    const float* Wo_w = (const float*)d_in[3];
    const float* Wo_b = (const float*)d_in[4];

    convert_w<<<(DD * DD / 4) / 256, 256>>>(Wo_w);
    const int cvblocks = (BB * SS * DD / 4) / (256 * 4);   // 1024
    convert_k<<<cvblocks, 256>>>(K);
    convert_v<<<cvblocks, 256>>>(V);

    cudaFuncSetAttribute(attn_mma, cudaFuncAttributeMaxDynamicSharedMemorySize, SMEM_BYTES);
    dim3 agrid(SS / BM, HH, BB);          // (32, 16, 2)
    attn_mma<<<agrid, 128, SMEM_BYTES>>>(Q);

    dim3 mgrid(HH, BB);
    meanv_fix<<<mgrid, 256>>>(V);

    dim3 pgrid(DD / 64, (BB * SS) / 128); // (16, 32)
    proj_mma2<<<pgrid, 256>>>(Wo_b, (float*)d_out);
}

// round 9
// speedup vs baseline: 1.7049x; 1.1535x over previous
#include <cuda_runtime.h>
#include <cuda_fp16.h>
#include <math.h>
#include <stdint.h>

// Problem constants
#define BB 2
#define SS 2048
#define DD 1024
#define HH 16
#define DQ 64

// Attention tiling
#define BM 64
#define BN 64

// ctx scratch, split fp16 hi/lo
__device__ __half g_ctx_h[BB * SS * DD];
__device__ __half g_ctx_l[BB * SS * DD];
// W hi fp16
__device__ __half g_w_h[DD * DD];
// K hi; V hi/lo  (K_lo not needed: QK keeps qh*kh + ql*kh only)
__device__ __half g_k_h[BB * SS * DD];
__device__ __half g_v_h[BB * SS * DD];
__device__ __half g_v_l[BB * SS * DD];

// ===========================================================================
// Helpers
// ===========================================================================
__device__ __forceinline__ uint32_t smem_u32(const void* p) {
    uint32_t a;
    asm("{ .reg .u64 t; cvta.to.shared.u64 t, %1; cvt.u32.u64 %0, t; }" : "=r"(a) : "l"(p));
    return a;
}
__device__ __forceinline__ uint32_t swz(uint32_t off) {
    return off ^ ((off >> 3) & 0x70);
}
__device__ __forceinline__ void ldsm4(uint32_t* r, uint32_t addr) {
    asm volatile("ldmatrix.sync.aligned.m8n8.x4.shared.b16 {%0,%1,%2,%3}, [%4];"
                 : "=r"(r[0]), "=r"(r[1]), "=r"(r[2]), "=r"(r[3]) : "r"(addr));
}
__device__ __forceinline__ void ldsm4t(uint32_t* r, uint32_t addr) {
    asm volatile("ldmatrix.sync.aligned.m8n8.x4.trans.shared.b16 {%0,%1,%2,%3}, [%4];"
                 : "=r"(r[0]), "=r"(r[1]), "=r"(r[2]), "=r"(r[3]) : "r"(addr));
}
__device__ __forceinline__ void mma16816(float* c, const uint32_t* a, uint32_t b0, uint32_t b1) {
    asm volatile("mma.sync.aligned.m16n8k16.row.col.f32.f16.f16.f32 "
                 "{%0,%1,%2,%3}, {%4,%5,%6,%7}, {%8,%9}, {%0,%1,%2,%3};"
                 : "+f"(c[0]), "+f"(c[1]), "+f"(c[2]), "+f"(c[3])
                 : "r"(a[0]), "r"(a[1]), "r"(a[2]), "r"(a[3]), "r"(b0), "r"(b1));
}
__device__ __forceinline__ void split2h(float x, float y, uint32_t& hi, uint32_t& lo) {
    __half2 h = __floats2half2_rn(x, y);
    float rx = x - __low2float(h);
    float ry = y - __high2float(h);
    __half2 l = __floats2half2_rn(rx, ry);
    hi = *reinterpret_cast<uint32_t*>(&h);
    lo = *reinterpret_cast<uint32_t*>(&l);
}
__device__ __forceinline__ void split4h(float4 v, uint2& hi, uint2& lo) {
    split2h(v.x, v.y, hi.x, lo.x);
    split2h(v.z, v.w, hi.y, lo.y);
}
__device__ __forceinline__ uint32_t pack2h(float x, float y) {
    __half2 h = __floats2half2_rn(x, y);
    return *reinterpret_cast<uint32_t*>(&h);
}
__device__ __forceinline__ void cpa16(uint32_t d, const void* s) {
    asm volatile("cp.async.cg.shared.global [%0], [%1], 16;" :: "r"(d), "l"(s));
}
#define CP_COMMIT() asm volatile("cp.async.commit_group;" ::: "memory")
#define CP_WAIT0()  asm volatile("cp.async.wait_group 0;" ::: "memory")
#define CP_WAIT1()  asm volatile("cp.async.wait_group 1;" ::: "memory")

// ===========================================================================
// W pre-split (hi only)
// ===========================================================================
extern "C" __global__ void __launch_bounds__(256)
convert_w(const float* __restrict__ W)
{
    int i = blockIdx.x * 256 + threadIdx.x;
    float4 v = reinterpret_cast<const float4*>(W)[i];
    uint2 hi, lo;
    split4h(v, hi, lo);
    reinterpret_cast<uint2*>(g_w_h)[i] = hi;
}

// ===========================================================================
// K convert (hi only), V convert (hi+lo). 8 float4 per thread, loads batched
// front (MLP=8) before stores. 512 blocks x 256 threads covers 1M float4.
// ===========================================================================
extern "C" __global__ void __launch_bounds__(256)
convert_k(const float* __restrict__ src)
{
    int i0 = (blockIdx.x * 256 + threadIdx.x) * 8;
    float4 v[8];
#pragma unroll
    for (int j = 0; j < 8; j++) v[j] = reinterpret_cast<const float4*>(src)[i0 + j];
#pragma unroll
    for (int j = 0; j < 8; j++) {
        uint2 hi, lo;
        split4h(v[j], hi, lo);
        reinterpret_cast<uint2*>(g_k_h)[i0 + j] = hi;
    }
}
extern "C" __global__ void __launch_bounds__(256)
convert_v(const float* __restrict__ src)
{
    int i0 = (blockIdx.x * 256 + threadIdx.x) * 8;
    float4 v[8];
#pragma unroll
    for (int j = 0; j < 8; j++) v[j] = reinterpret_cast<const float4*>(src)[i0 + j];
#pragma unroll
    for (int j = 0; j < 8; j++) {
        uint2 hi, lo;
        split4h(v[j], hi, lo);
        reinterpret_cast<uint2*>(g_v_h)[i0 + j] = hi;
        reinterpret_cast<uint2*>(g_v_l)[i0 + j] = lo;
    }
}

// ===========================================================================
// Row-0 fix: reference row q=0 fully masked -> uniform softmax -> ctx = mean V.
// ===========================================================================
extern "C" __global__ void __launch_bounds__(256)
meanv_fix(const float* __restrict__ V)
{
    __shared__ float red[256];
    const int h = blockIdx.x, b = blockIdx.y;
    const int t = threadIdx.x;
    const int d = t & 63;
    const int sc = t >> 6;
    const float* src = V + (size_t)b * SS * DD + h * DQ + d;
    float s = 0.0f;
#pragma unroll 8
    for (int i = sc * 512; i < sc * 512 + 512; i++)
        s += src[(size_t)i * DD];
    red[t] = s;
    __syncthreads();
    if (t < 64) {
        float m = (red[t] + red[t + 64] + red[t + 128] + red[t + 192]) * (1.0f / 2048.0f);
        size_t idx = (size_t)b * SS * DD + h * DQ + d;
        __half hh = __float2half_rn(m);
        g_ctx_h[idx] = hh;
        g_ctx_l[idx] = __float2half_rn(m - __half2float(hh));
    }
}

// ===========================================================================
// Attention smem: Q hi/lo (16 KB) + 2 stages x (KH, VH, VL) (24 KB each).
// ===========================================================================
#define SM_QH   0
#define SM_QL   8192
#define SM_STG  16384
#define STG_STR 24576
#define SMEM_BYTES 65536

// ===========================================================================
// Flash attention: fp16 HMMA, pipelined K/V (2-stage cp.async).
// QK 2-term (qh*kh + ql*kh), PV 2-term (p*vh + p*vl).
// 128 threads (4 warps x 16 query rows). Grid (32, 16, 2).
// ===========================================================================
extern "C" __global__ void __launch_bounds__(128)
attn_mma(const float* __restrict__ Q)
{
    extern __shared__ char smc[];
    const uint32_t sb = smem_u32(smc);
    const int tid  = threadIdx.x;
    const int lane = tid & 31;
    const int wid  = tid >> 5;

    const int bx = blockIdx.x;
    const int qt = (bx == 31) ? 0 : (31 - bx);
    const int h  = blockIdx.y;
    const int b  = blockIdx.z;
    const int q0 = qt * BM;

    const float* Qb  = Q + ((size_t)(b * SS + q0)) * DD + h * DQ;
    const size_t kvb = (size_t)b * SS * DD + h * DQ;

    const int nkt = qt + 1;

    // cp.async chunk coords (512 chunks per 8-KB tile, 4 per thread per array)
    const int cr = tid >> 1;
    const int cg = (tid & 1) * 4;

    auto prefetch = [&](int stage, int k0) {
        const uint32_t stg = sb + SM_STG + stage * STG_STR;
#pragma unroll
        for (int q = 0; q < 4; q++) {
            const int g = cg + q;
            const uint32_t off = swz((uint32_t)(cr * 128 + g * 16));
            const size_t srco = kvb + (size_t)(k0 + cr) * DD + g * 8;
            cpa16(stg + off,         &g_k_h[srco]);
            cpa16(stg + 8192 + off,  &g_v_h[srco]);
            cpa16(stg + 16384 + off, &g_v_l[srco]);
        }
    };

    prefetch(0, 0);
    CP_COMMIT();

    // ---- Load Q tile (overlaps with stage-0 prefetch) ----
#pragma unroll
    for (int it = 0; it < 8; it++) {
        int idx = it * 128 + tid;
        int r = idx >> 4;
        int g = idx & 15;
        float4 q4 = *reinterpret_cast<const float4*>(Qb + (size_t)r * DD + g * 4);
        uint2 hi, lo;
        split4h(q4, hi, lo);
        uint32_t off = swz((uint32_t)(r * 128 + g * 8));
        *reinterpret_cast<uint2*>(smc + SM_QH + off) = hi;
        *reinterpret_cast<uint2*>(smc + SM_QL + off) = lo;
    }

    float Oa[32];
    float l0 = 0.0f, l1 = 0.0f;
#pragma unroll
    for (int i = 0; i < 32; i++) Oa[i] = 0.0f;

    const int qg0 = q0 + wid * 16 + (lane >> 2);
    const int qg1 = qg0 + 8;

    for (int kt = 0; kt < nkt; kt++) {
        const int k0 = kt * BN;

        if (kt + 1 < nkt) {
            prefetch((kt + 1) & 1, k0 + BN);
            CP_COMMIT();
            CP_WAIT1();
        } else {
            CP_WAIT0();
        }
        __syncthreads();

        const uint32_t stg = sb + SM_STG + (kt & 1) * STG_STR;

        // ---- S = Q K^T : 2-term (qh*kh + ql*kh) ----
        float sc[32];
#pragma unroll
        for (int i = 0; i < 32; i++) sc[i] = 0.0f;

#pragma unroll
        for (int kc = 0; kc < 4; kc++) {
            uint32_t ah[4], al[4];
            uint32_t offA = swz((uint32_t)((wid * 16 + (lane & 15)) * 128 +
                                           (kc * 16 + (lane >> 4) * 8) * 2));
            ldsm4(ah, sb + SM_QH + offA);
            ldsm4(al, sb + SM_QL + offA);
#pragma unroll
            for (int nt4 = 0; nt4 < 4; nt4++) {
                uint32_t offB = swz((uint32_t)((nt4 * 16 + (lane & 7) + ((lane >> 4) << 3)) * 128 +
                                               (kc * 16 + ((lane >> 3) & 1) * 8) * 2));
                uint32_t bh[4];
                ldsm4(bh, stg + offB);
                float* c0 = &sc[nt4 * 8];
                float* c1 = &sc[nt4 * 8 + 4];
                mma16816(c0, ah, bh[0], bh[1]);   // qh*kh
                mma16816(c1, ah, bh[2], bh[3]);
                mma16816(c0, al, bh[0], bh[1]);   // ql*kh
                mma16816(c1, al, bh[2], bh[3]);
            }
        }

        // ---- softmax: masked -> 0 exactly; single-fp16 P ----
        uint32_t pf[16];
#pragma unroll
        for (int nt = 0; nt < 8; nt++) {
            const int kg = k0 + nt * 8 + 2 * (lane & 3);
            float p0 = (kg     >= qg0) ? 0.0f : __expf(sc[nt * 4 + 0] * 0.125f);
            float p1 = (kg + 1 >= qg0) ? 0.0f : __expf(sc[nt * 4 + 1] * 0.125f);
            float p2 = (kg     >= qg1) ? 0.0f : __expf(sc[nt * 4 + 2] * 0.125f);
            float p3 = (kg + 1 >= qg1) ? 0.0f : __expf(sc[nt * 4 + 3] * 0.125f);
            l0 += p0 + p1;
            l1 += p2 + p3;
            pf[nt * 2 + 0] = pack2h(p0, p1);
            pf[nt * 2 + 1] = pack2h(p2, p3);
        }

        // ---- O += P V : 2-term (P x V_hi + P x V_lo) ----
#pragma unroll
        for (int c = 0; c < 4; c++) {
            const uint32_t* pa = &pf[c * 4];
#pragma unroll
            for (int d4 = 0; d4 < 4; d4++) {
                uint32_t offV = swz((uint32_t)((c * 16 + (lane & 7) + ((lane >> 3) & 1) * 8) * 128 +
                                               (d4 * 16 + (lane >> 4) * 8) * 2));
                uint32_t bh[4], bl[4];
                ldsm4t(bh, stg + 8192 + offV);
                ldsm4t(bl, stg + 16384 + offV);
                float* o0 = &Oa[d4 * 8];
                float* o1 = &Oa[d4 * 8 + 4];
                mma16816(o0, pa, bh[0], bh[1]);
                mma16816(o1, pa, bh[2], bh[3]);
                mma16816(o0, pa, bl[0], bl[1]);
                mma16816(o1, pa, bl[2], bl[3]);
            }
        }
        __syncthreads();   // all warps done with stage (kt&1) before its reuse
    }

    // ---- Epilogue ----
    l0 += __shfl_xor_sync(0xffffffffu, l0, 1);
    l0 += __shfl_xor_sync(0xffffffffu, l0, 2);
    l1 += __shfl_xor_sync(0xffffffffu, l1, 1);
    l1 += __shfl_xor_sync(0xffffffffu, l1, 2);
    const float inv0 = (l0 > 0.0f) ? 1.0f / l0 : 0.0f;   // row 0 overwritten by meanv_fix
    const float inv1 = 1.0f / l1;

    const int row0 = q0 + wid * 16 + (lane >> 2);
    const size_t base0 = ((size_t)(b * SS + row0)) * DD + h * DQ;
    const size_t base1 = base0 + (size_t)8 * DD;
#pragma unroll
    for (int nt = 0; nt < 8; nt++) {
        const int col = nt * 8 + 2 * (lane & 3);
        uint32_t hi, lo;
        split2h(Oa[nt * 4 + 0] * inv0, Oa[nt * 4 + 1] * inv0, hi, lo);
        *reinterpret_cast<uint32_t*>(&g_ctx_h[base0 + col]) = hi;
        *reinterpret_cast<uint32_t*>(&g_ctx_l[base0 + col]) = lo;
        split2h(Oa[nt * 4 + 2] * inv1, Oa[nt * 4 + 3] * inv1, hi, lo);
        *reinterpret_cast<uint32_t*>(&g_ctx_h[base1 + col]) = hi;
        *reinterpret_cast<uint32_t*>(&g_ctx_l[base1 + col]) = lo;
    }
}

// ===========================================================================
// Projection (unchanged from R8): fp16 2-term, CTA 128x64, BK=32, 256 thr.
// ===========================================================================
#define PNIT (DD / 32)

extern "C" __global__ void __launch_bounds__(256, 2)
proj_mma2(const float* __restrict__ bias,
          float* __restrict__ out)
{
    __shared__ __align__(16) char sA[2][16384];
    __shared__ __align__(16) char sB[2][8192];

    const int tid  = threadIdx.x;
    const int lane = tid & 31;
    const int wid  = tid >> 5;
    const int wm   = wid >> 1;
    const int wn   = wid & 1;
    const int j0   = blockIdx.x * 64;
    const int i0   = blockIdx.y * 128;

    const uint32_t sa0 = smem_u32(sA[0]);
    const uint32_t sa1 = smem_u32(sA[1]);
    const uint32_t sb0 = smem_u32(sB[0]);
    const uint32_t sb1 = smem_u32(sB[1]);

    float acc[32];
#pragma unroll
    for (int i = 0; i < 32; i++) acc[i] = 0.0f;

    auto issue = [&](int stage, int k0) {
        const uint32_t sa = stage ? sa1 : sa0;
        const uint32_t sbm = stage ? sb1 : sb0;
#pragma unroll
        for (int q = 0; q < 4; q++) {
            int id = q * 256 + tid;
            int r = id >> 3;
            int g = id & 7;
            const __half* src = (g < 4)
                ? &g_ctx_h[(size_t)(i0 + r) * DD + k0 + g * 8]
                : &g_ctx_l[(size_t)(i0 + r) * DD + k0 + (g - 4) * 8];
            cpa16(sa + swz((uint32_t)(r * 128 + g * 16)), src);
        }
        {
            int r = tid >> 2;
            int g = tid & 3;
            cpa16(sbm + swz((uint32_t)(r * 128 + g * 16)),
                  &g_w_h[(size_t)(j0 + r) * DD + k0 + g * 8]);
        }
    };

    issue(0, 0);  CP_COMMIT();
    issue(1, 32); CP_COMMIT();

    for (int it = 0; it < PNIT; it++) {
        CP_WAIT1();
        __syncthreads();
        const uint32_t sa = (it & 1) ? sa1 : sa0;
        const uint32_t sbm = (it & 1) ? sb1 : sb0;

#pragma unroll
        for (int kc = 0; kc < 2; kc++) {
            const int kk = kc * 16;
            uint32_t ah[2][4], al[2][4];
#pragma unroll
            for (int m = 0; m < 2; m++) {
                const uint32_t row = wm * 32 + m * 16 + (lane & 15);
                const uint32_t colb = (kk + (lane >> 4) * 8) * 2;
                ldsm4(ah[m], sa + swz(row * 128 + colb));
                ldsm4(al[m], sa + swz(row * 128 + 64 + colb));
            }
            uint32_t bh[2][4];
#pragma unroll
            for (int nt = 0; nt < 2; nt++) {
                const uint32_t rowb = wn * 32 + nt * 16 + (lane & 7) + ((lane >> 4) << 3);
                const uint32_t colb = (kk + ((lane >> 3) & 1) * 8) * 2;
                ldsm4(bh[nt], sbm + swz(rowb * 128 + colb));
            }
#pragma unroll
            for (int m = 0; m < 2; m++)
#pragma unroll
                for (int nt = 0; nt < 2; nt++) {
                    float* c0 = &acc[(m * 2 + nt) * 8];
                    float* c1 = c0 + 4;
                    mma16816(c0, ah[m], bh[nt][0], bh[nt][1]);
                    mma16816(c1, ah[m], bh[nt][2], bh[nt][3]);
                    mma16816(c0, al[m], bh[nt][0], bh[nt][1]);
                    mma16816(c1, al[m], bh[nt][2], bh[nt][3]);
                }
        }

        __syncthreads();
        if (it + 2 < PNIT) {
            issue(it & 1, (it + 2) * 32);
        }
        CP_COMMIT();
    }

#pragma unroll
    for (int m = 0; m < 2; m++) {
        const int row = i0 + wm * 32 + m * 16 + (lane >> 2);
        float* d0 = out + (size_t)row * DD;
        float* d1 = d0 + (size_t)8 * DD;
#pragma unroll
        for (int nt = 0; nt < 2; nt++) {
#pragma unroll
            for (int n8 = 0; n8 < 2; n8++) {
                const int col = j0 + wn * 32 + nt * 16 + n8 * 8 + 2 * (lane & 3);
                const float* c = &acc[(m * 2 + nt) * 8 + n8 * 4];
                const float b0 = bias[col];
                const float b1 = bias[col + 1];
                *reinterpret_cast<float2*>(d0 + col) = make_float2(c[0] + b0, c[1] + b1);
                *reinterpret_cast<float2*>(d1 + col) = make_float2(c[2] + b0, c[3] + b1);
            }
        }
    }
}

// ===========================================================================
extern "C" void kernel_launch(void* const* d_in, const int* in_sizes, int n_in,
                              void* d_out, int out_size)
{
    const float* Q    = (const float*)d_in[0];
    const float* K    = (const float*)d_in[1];
    const float* V    = (const float*)d_in[2];
    const float* Wo_w = (const float*)d_in[3];
    const float* Wo_b = (const float*)d_in[4];

    convert_w<<<(DD * DD / 4) / 256, 256>>>(Wo_w);
    const int cvblocks = (BB * SS * DD / 4) / (256 * 8);   // 512
    convert_k<<<cvblocks, 256>>>(K);
    convert_v<<<cvblocks, 256>>>(V);

    cudaFuncSetAttribute(attn_mma, cudaFuncAttributeMaxDynamicSharedMemorySize, SMEM_BYTES);
    dim3 agrid(SS / BM, HH, BB);          // (32, 16, 2)
    attn_mma<<<agrid, 128, SMEM_BYTES>>>(Q);

    dim3 mgrid(HH, BB);
    meanv_fix<<<mgrid, 256>>>(V);

    dim3 pgrid(DD / 64, (BB * SS) / 128); // (16, 32)
    proj_mma2<<<pgrid, 256>>>(Wo_b, (float*)d_out);
}

// round 10
// speedup vs baseline: 1.8991x; 1.1139x over previous
#include <cuda_runtime.h>
#include <cuda_fp16.h>
#include <math.h>
#include <stdint.h>

// Problem constants
#define BB 2
#define SS 2048
#define DD 1024
#define HH 16
#define DQ 64

// Attention tiling
#define BM 64
#define BN 64

// ctx scratch, split fp16 hi/lo
__device__ __half g_ctx_h[BB * SS * DD];
__device__ __half g_ctx_l[BB * SS * DD];
// W hi fp16
__device__ __half g_w_h[DD * DD];
// K hi; V hi/lo
__device__ __half g_k_h[BB * SS * DD];
__device__ __half g_v_h[BB * SS * DD];
__device__ __half g_v_l[BB * SS * DD];

// ===========================================================================
// Helpers
// ===========================================================================
__device__ __forceinline__ uint32_t smem_u32(const void* p) {
    uint32_t a;
    asm("{ .reg .u64 t; cvta.to.shared.u64 t, %1; cvt.u32.u64 %0, t; }" : "=r"(a) : "l"(p));
    return a;
}
__device__ __forceinline__ uint32_t swz(uint32_t off) {
    return off ^ ((off >> 3) & 0x70);
}
__device__ __forceinline__ void ldsm4(uint32_t* r, uint32_t addr) {
    asm volatile("ldmatrix.sync.aligned.m8n8.x4.shared.b16 {%0,%1,%2,%3}, [%4];"
                 : "=r"(r[0]), "=r"(r[1]), "=r"(r[2]), "=r"(r[3]) : "r"(addr));
}
__device__ __forceinline__ void ldsm4t(uint32_t* r, uint32_t addr) {
    asm volatile("ldmatrix.sync.aligned.m8n8.x4.trans.shared.b16 {%0,%1,%2,%3}, [%4];"
                 : "=r"(r[0]), "=r"(r[1]), "=r"(r[2]), "=r"(r[3]) : "r"(addr));
}
__device__ __forceinline__ void mma16816(float* c, const uint32_t* a, uint32_t b0, uint32_t b1) {
    asm volatile("mma.sync.aligned.m16n8k16.row.col.f32.f16.f16.f32 "
                 "{%0,%1,%2,%3}, {%4,%5,%6,%7}, {%8,%9}, {%0,%1,%2,%3};"
                 : "+f"(c[0]), "+f"(c[1]), "+f"(c[2]), "+f"(c[3])
                 : "r"(a[0]), "r"(a[1]), "r"(a[2]), "r"(a[3]), "r"(b0), "r"(b1));
}
__device__ __forceinline__ void split2h(float x, float y, uint32_t& hi, uint32_t& lo) {
    __half2 h = __floats2half2_rn(x, y);
    float rx = x - __low2float(h);
    float ry = y - __high2float(h);
    __half2 l = __floats2half2_rn(rx, ry);
    hi = *reinterpret_cast<uint32_t*>(&h);
    lo = *reinterpret_cast<uint32_t*>(&l);
}
__device__ __forceinline__ void split4h(float4 v, uint2& hi, uint2& lo) {
    split2h(v.x, v.y, hi.x, lo.x);
    split2h(v.z, v.w, hi.y, lo.y);
}
__device__ __forceinline__ uint32_t pack2h(float x, float y) {
    __half2 h = __floats2half2_rn(x, y);
    return *reinterpret_cast<uint32_t*>(&h);
}
__device__ __forceinline__ void cpa16(uint32_t d, const void* s) {
    asm volatile("cp.async.cg.shared.global [%0], [%1], 16;" :: "r"(d), "l"(s));
}
#define CP_COMMIT() asm volatile("cp.async.commit_group;" ::: "memory")
#define CP_WAIT0()  asm volatile("cp.async.wait_group 0;" ::: "memory")
#define CP_WAIT1()  asm volatile("cp.async.wait_group 1;" ::: "memory")

// ===========================================================================
// Converters
// ===========================================================================
extern "C" __global__ void __launch_bounds__(256)
convert_w(const float* __restrict__ W)
{
    int i = blockIdx.x * 256 + threadIdx.x;
    float4 v = reinterpret_cast<const float4*>(W)[i];
    uint2 hi, lo;
    split4h(v, hi, lo);
    reinterpret_cast<uint2*>(g_w_h)[i] = hi;
}
extern "C" __global__ void __launch_bounds__(256)
convert_k(const float* __restrict__ src)
{
    int i0 = (blockIdx.x * 256 + threadIdx.x) * 8;
    float4 v[8];
#pragma unroll
    for (int j = 0; j < 8; j++) v[j] = reinterpret_cast<const float4*>(src)[i0 + j];
#pragma unroll
    for (int j = 0; j < 8; j++) {
        uint2 hi, lo;
        split4h(v[j], hi, lo);
        reinterpret_cast<uint2*>(g_k_h)[i0 + j] = hi;
    }
}
extern "C" __global__ void __launch_bounds__(256)
convert_v(const float* __restrict__ src)
{
    int i0 = (blockIdx.x * 256 + threadIdx.x) * 8;
    float4 v[8];
#pragma unroll
    for (int j = 0; j < 8; j++) v[j] = reinterpret_cast<const float4*>(src)[i0 + j];
#pragma unroll
    for (int j = 0; j < 8; j++) {
        uint2 hi, lo;
        split4h(v[j], hi, lo);
        reinterpret_cast<uint2*>(g_v_h)[i0 + j] = hi;
        reinterpret_cast<uint2*>(g_v_l)[i0 + j] = lo;
    }
}

// ===========================================================================
// Row-0 fix: ctx(q=0) = mean_s V (fully-masked row -> uniform softmax)
// ===========================================================================
extern "C" __global__ void __launch_bounds__(256)
meanv_fix(const float* __restrict__ V)
{
    __shared__ float red[256];
    const int h = blockIdx.x, b = blockIdx.y;
    const int t = threadIdx.x;
    const int d = t & 63;
    const int sc = t >> 6;
    const float* src = V + (size_t)b * SS * DD + h * DQ + d;
    float s = 0.0f;
#pragma unroll 8
    for (int i = sc * 512; i < sc * 512 + 512; i++)
        s += src[(size_t)i * DD];
    red[t] = s;
    __syncthreads();
    if (t < 64) {
        float m = (red[t] + red[t + 64] + red[t + 128] + red[t + 192]) * (1.0f / 2048.0f);
        size_t idx = (size_t)b * SS * DD + h * DQ + d;
        __half hh = __float2half_rn(m);
        g_ctx_h[idx] = hh;
        g_ctx_l[idx] = __float2half_rn(m - __half2float(hh));
    }
}

// ===========================================================================
// Attention smem: Q hi/lo (16 KB) + 2 stages x (KH, VH, VL) (24 KB each).
// Cross-warp reduce buffer reuses [0, 18 KB) after the main loop.
// ===========================================================================
#define SM_QH   0
#define SM_QL   8192
#define SM_STG  16384
#define STG_STR 24576
#define SMEM_BYTES 65536
#define RED_STR 35   // floats per lane slot (33 O-pad + 2 l), conflict-free

// ===========================================================================
// Flash attention: fp16 HMMA, pipelined K/V, 8 warps (16 rows x 32 keys each;
// key-half partial O accumulated across tiles, summed once in epilogue).
// QK 2-term (qh*kh + ql*kh), PV 2-term (p*vh + p*vl). Grid (32,16,2), 256 thr.
// ===========================================================================
extern "C" __global__ void __launch_bounds__(256, 2)
attn_mma(const float* __restrict__ Q)
{
    extern __shared__ char smc[];
    const uint32_t sb = smem_u32(smc);
    const int tid  = threadIdx.x;
    const int lane = tid & 31;
    const int wid  = tid >> 5;
    const int wr   = wid >> 1;    // row group 0..3
    const int wk   = wid & 1;     // key half 0..1

    const int bx = blockIdx.x;
    const int qt = (bx == 31) ? 0 : (31 - bx);
    const int h  = blockIdx.y;
    const int b  = blockIdx.z;
    const int q0 = qt * BM;

    const float* Qb  = Q + ((size_t)(b * SS + q0)) * DD + h * DQ;
    const size_t kvb = (size_t)b * SS * DD + h * DQ;

    const int nkt = qt + 1;

    auto prefetch = [&](int stage, int k0) {
        const uint32_t stg = sb + SM_STG + stage * STG_STR;
#pragma unroll
        for (int q = 0; q < 2; q++) {
            const int id = q * 256 + tid;     // 0..511
            const int r = id >> 3;
            const int g = id & 7;
            const uint32_t off = swz((uint32_t)(r * 128 + g * 16));
            const size_t srco = kvb + (size_t)(k0 + r) * DD + g * 8;
            cpa16(stg + off,         &g_k_h[srco]);
            cpa16(stg + 8192 + off,  &g_v_h[srco]);
            cpa16(stg + 16384 + off, &g_v_l[srco]);
        }
    };

    prefetch(0, 0);
    CP_COMMIT();

    // ---- Load Q tile (overlaps stage-0 prefetch) ----
#pragma unroll
    for (int it = 0; it < 4; it++) {
        int idx = it * 256 + tid;
        int r = idx >> 4;
        int g = idx & 15;
        float4 q4 = *reinterpret_cast<const float4*>(Qb + (size_t)r * DD + g * 4);
        uint2 hi, lo;
        split4h(q4, hi, lo);
        uint32_t off = swz((uint32_t)(r * 128 + g * 8));
        *reinterpret_cast<uint2*>(smc + SM_QH + off) = hi;
        *reinterpret_cast<uint2*>(smc + SM_QL + off) = lo;
    }

    float Oa[32];
    float l0 = 0.0f, l1 = 0.0f;
#pragma unroll
    for (int i = 0; i < 32; i++) Oa[i] = 0.0f;

    const int qg0 = q0 + wr * 16 + (lane >> 2);
    const int qg1 = qg0 + 8;

    for (int kt = 0; kt < nkt; kt++) {
        const int k0 = kt * BN;

        if (kt + 1 < nkt) {
            prefetch((kt + 1) & 1, k0 + BN);
            CP_COMMIT();
            CP_WAIT1();
        } else {
            CP_WAIT0();
        }
        __syncthreads();

        const uint32_t stg = sb + SM_STG + (kt & 1) * STG_STR;

        // ---- S(16x32) = Q K^T : 2-term (qh*kh + ql*kh) ----
        float sc[16];
#pragma unroll
        for (int i = 0; i < 16; i++) sc[i] = 0.0f;

#pragma unroll
        for (int kc = 0; kc < 4; kc++) {
            uint32_t ah[4], al[4];
            uint32_t offA = swz((uint32_t)((wr * 16 + (lane & 15)) * 128 +
                                           (kc * 16 + (lane >> 4) * 8) * 2));
            ldsm4(ah, sb + SM_QH + offA);
            ldsm4(al, sb + SM_QL + offA);
#pragma unroll
            for (int nt4 = 0; nt4 < 2; nt4++) {
                uint32_t offB = swz((uint32_t)((wk * 32 + nt4 * 16 + (lane & 7) + ((lane >> 4) << 3)) * 128 +
                                               (kc * 16 + ((lane >> 3) & 1) * 8) * 2));
                uint32_t bh[4];
                ldsm4(bh, stg + offB);
                float* c0 = &sc[nt4 * 8];
                float* c1 = &sc[nt4 * 8 + 4];
                mma16816(c0, ah, bh[0], bh[1]);   // qh*kh
                mma16816(c1, ah, bh[2], bh[3]);
                mma16816(c0, al, bh[0], bh[1]);   // ql*kh
                mma16816(c1, al, bh[2], bh[3]);
            }
        }

        // ---- softmax (masked -> 0 exactly); single-fp16 P ----
        uint32_t pf[8];
#pragma unroll
        for (int nt = 0; nt < 4; nt++) {
            const int kg = k0 + wk * 32 + nt * 8 + 2 * (lane & 3);
            float p0 = (kg     >= qg0) ? 0.0f : __expf(sc[nt * 4 + 0] * 0.125f);
            float p1 = (kg + 1 >= qg0) ? 0.0f : __expf(sc[nt * 4 + 1] * 0.125f);
            float p2 = (kg     >= qg1) ? 0.0f : __expf(sc[nt * 4 + 2] * 0.125f);
            float p3 = (kg + 1 >= qg1) ? 0.0f : __expf(sc[nt * 4 + 3] * 0.125f);
            l0 += p0 + p1;
            l1 += p2 + p3;
            pf[nt * 2 + 0] = pack2h(p0, p1);
            pf[nt * 2 + 1] = pack2h(p2, p3);
        }

        // ---- O(partial over key-half) += P V ----
#pragma unroll
        for (int c = 0; c < 2; c++) {
            const uint32_t* pa = &pf[c * 4];
#pragma unroll
            for (int d4 = 0; d4 < 4; d4++) {
                uint32_t offV = swz((uint32_t)((wk * 32 + c * 16 + (lane & 7) + ((lane >> 3) & 1) * 8) * 128 +
                                               (d4 * 16 + (lane >> 4) * 8) * 2));
                uint32_t bh[4], bl[4];
                ldsm4t(bh, stg + 8192 + offV);
                ldsm4t(bl, stg + 16384 + offV);
                float* o0 = &Oa[d4 * 8];
                float* o1 = &Oa[d4 * 8 + 4];
                mma16816(o0, pa, bh[0], bh[1]);
                mma16816(o1, pa, bh[2], bh[3]);
                mma16816(o0, pa, bl[0], bl[1]);
                mma16816(o1, pa, bl[2], bl[3]);
            }
        }
        __syncthreads();
    }

    // ---- Cross-warp (key-half) reduction via smem ----
    float* sred = reinterpret_cast<float*>(smc);   // [4][32][RED_STR]
    float* slot = sred + (wr * 32 + lane) * RED_STR;
    if (wk == 1) {
#pragma unroll
        for (int i = 0; i < 32; i++) slot[i] = Oa[i];
        slot[32] = l0;
        slot[33] = l1;
    }
    __syncthreads();
    if (wk == 0) {
#pragma unroll
        for (int i = 0; i < 32; i++) Oa[i] += slot[i];
        l0 += slot[32];
        l1 += slot[33];

        l0 += __shfl_xor_sync(0xffffffffu, l0, 1);
        l0 += __shfl_xor_sync(0xffffffffu, l0, 2);
        l1 += __shfl_xor_sync(0xffffffffu, l1, 1);
        l1 += __shfl_xor_sync(0xffffffffu, l1, 2);
        const float inv0 = (l0 > 0.0f) ? 1.0f / l0 : 0.0f;   // row 0 overwritten by meanv_fix
        const float inv1 = 1.0f / l1;

        const int row0 = q0 + wr * 16 + (lane >> 2);
        const size_t base0 = ((size_t)(b * SS + row0)) * DD + h * DQ;
        const size_t base1 = base0 + (size_t)8 * DD;
#pragma unroll
        for (int nt = 0; nt < 8; nt++) {
            const int col = nt * 8 + 2 * (lane & 3);
            uint32_t hi, lo;
            split2h(Oa[nt * 4 + 0] * inv0, Oa[nt * 4 + 1] * inv0, hi, lo);
            *reinterpret_cast<uint32_t*>(&g_ctx_h[base0 + col]) = hi;
            *reinterpret_cast<uint32_t*>(&g_ctx_l[base0 + col]) = lo;
            split2h(Oa[nt * 4 + 2] * inv1, Oa[nt * 4 + 3] * inv1, hi, lo);
            *reinterpret_cast<uint32_t*>(&g_ctx_h[base1 + col]) = hi;
            *reinterpret_cast<uint32_t*>(&g_ctx_l[base1 + col]) = lo;
        }
    }
}

// ===========================================================================
// Projection (unchanged from R9): fp16 2-term, CTA 128x64, BK=32, 256 thr.
// ===========================================================================
#define PNIT (DD / 32)

extern "C" __global__ void __launch_bounds__(256, 2)
proj_mma2(const float* __restrict__ bias,
          float* __restrict__ out)
{
    __shared__ __align__(16) char sA[2][16384];
    __shared__ __align__(16) char sB[2][8192];

    const int tid  = threadIdx.x;
    const int lane = tid & 31;
    const int wid  = tid >> 5;
    const int wm   = wid >> 1;
    const int wn   = wid & 1;
    const int j0   = blockIdx.x * 64;
    const int i0   = blockIdx.y * 128;

    const uint32_t sa0 = smem_u32(sA[0]);
    const uint32_t sa1 = smem_u32(sA[1]);
    const uint32_t sb0 = smem_u32(sB[0]);
    const uint32_t sb1 = smem_u32(sB[1]);

    float acc[32];
#pragma unroll
    for (int i = 0; i < 32; i++) acc[i] = 0.0f;

    auto issue = [&](int stage, int k0) {
        const uint32_t sa = stage ? sa1 : sa0;
        const uint32_t sbm = stage ? sb1 : sb0;
#pragma unroll
        for (int q = 0; q < 4; q++) {
            int id = q * 256 + tid;
            int r = id >> 3;
            int g = id & 7;
            const __half* src = (g < 4)
                ? &g_ctx_h[(size_t)(i0 + r) * DD + k0 + g * 8]
                : &g_ctx_l[(size_t)(i0 + r) * DD + k0 + (g - 4) * 8];
            cpa16(sa + swz((uint32_t)(r * 128 + g * 16)), src);
        }
        {
            int r = tid >> 2;
            int g = tid & 3;
            cpa16(sbm + swz((uint32_t)(r * 128 + g * 16)),
                  &g_w_h[(size_t)(j0 + r) * DD + k0 + g * 8]);
        }
    };

    issue(0, 0);  CP_COMMIT();
    issue(1, 32); CP_COMMIT();

    for (int it = 0; it < PNIT; it++) {
        CP_WAIT1();
        __syncthreads();
        const uint32_t sa = (it & 1) ? sa1 : sa0;
        const uint32_t sbm = (it & 1) ? sb1 : sb0;

#pragma unroll
        for (int kc = 0; kc < 2; kc++) {
            const int kk = kc * 16;
            uint32_t ah[2][4], al[2][4];
#pragma unroll
            for (int m = 0; m < 2; m++) {
                const uint32_t row = wm * 32 + m * 16 + (lane & 15);
                const uint32_t colb = (kk + (lane >> 4) * 8) * 2;
                ldsm4(ah[m], sa + swz(row * 128 + colb));
                ldsm4(al[m], sa + swz(row * 128 + 64 + colb));
            }
            uint32_t bh[2][4];
#pragma unroll
            for (int nt = 0; nt < 2; nt++) {
                const uint32_t rowb = wn * 32 + nt * 16 + (lane & 7) + ((lane >> 4) << 3);
                const uint32_t colb = (kk + ((lane >> 3) & 1) * 8) * 2;
                ldsm4(bh[nt], sbm + swz(rowb * 128 + colb));
            }
#pragma unroll
            for (int m = 0; m < 2; m++)
#pragma unroll
                for (int nt = 0; nt < 2; nt++) {
                    float* c0 = &acc[(m * 2 + nt) * 8];
                    float* c1 = c0 + 4;
                    mma16816(c0, ah[m], bh[nt][0], bh[nt][1]);
                    mma16816(c1, ah[m], bh[nt][2], bh[nt][3]);
                    mma16816(c0, al[m], bh[nt][0], bh[nt][1]);
                    mma16816(c1, al[m], bh[nt][2], bh[nt][3]);
                }
        }

        __syncthreads();
        if (it + 2 < PNIT) {
            issue(it & 1, (it + 2) * 32);
        }
        CP_COMMIT();
    }

#pragma unroll
    for (int m = 0; m < 2; m++) {
        const int row = i0 + wm * 32 + m * 16 + (lane >> 2);
        float* d0 = out + (size_t)row * DD;
        float* d1 = d0 + (size_t)8 * DD;
#pragma unroll
        for (int nt = 0; nt < 2; nt++) {
#pragma unroll
            for (int n8 = 0; n8 < 2; n8++) {
                const int col = j0 + wn * 32 + nt * 16 + n8 * 8 + 2 * (lane & 3);
                const float* c = &acc[(m * 2 + nt) * 8 + n8 * 4];
                const float b0 = bias[col];
                const float b1 = bias[col + 1];
                *reinterpret_cast<float2*>(d0 + col) = make_float2(c[0] + b0, c[1] + b1);
                *reinterpret_cast<float2*>(d1 + col) = make_float2(c[2] + b0, c[3] + b1);
            }
        }
    }
}

// ===========================================================================
extern "C" void kernel_launch(void* const* d_in, const int* in_sizes, int n_in,
                              void* d_out, int out_size)
{
    const float* Q    = (const float*)d_in[0];
    const float* K    = (const float*)d_in[1];
    const float* V    = (const float*)d_in[2];
    const float* Wo_w = (const float*)d_in[3];
    const float* Wo_b = (const float*)d_in[4];

    convert_w<<<(DD * DD / 4) / 256, 256>>>(Wo_w);
    const int cvblocks = (BB * SS * DD / 4) / (256 * 8);   // 512
    convert_k<<<cvblocks, 256>>>(K);
    convert_v<<<cvblocks, 256>>>(V);

    cudaFuncSetAttribute(attn_mma, cudaFuncAttributeMaxDynamicSharedMemorySize, SMEM_BYTES);
    dim3 agrid(SS / BM, HH, BB);          // (32, 16, 2)
    attn_mma<<<agrid, 256, SMEM_BYTES>>>(Q);

    dim3 mgrid(HH, BB);
    meanv_fix<<<mgrid, 256>>>(V);

    dim3 pgrid(DD / 64, (BB * SS) / 128); // (16, 32)
    proj_mma2<<<pgrid, 256>>>(Wo_b, (float*)d_out);
}

// round 11
// speedup vs baseline: 2.0989x; 1.1052x over previous
#include <cuda_runtime.h>
#include <cuda_fp16.h>
#include <math.h>
#include <stdint.h>

// Problem constants
#define BB 2
#define SS 2048
#define DD 1024
#define HH 16
#define DQ 64

// Attention tiling
#define BM 64
#define BN 64

// ctx scratch, split fp16 hi/lo
__device__ __half g_ctx_h[BB * SS * DD];
__device__ __half g_ctx_l[BB * SS * DD];
// W hi fp16
__device__ __half g_w_h[DD * DD];
// K hi; V hi/lo
__device__ __half g_k_h[BB * SS * DD];
__device__ __half g_v_h[BB * SS * DD];
__device__ __half g_v_l[BB * SS * DD];

// ===========================================================================
// Helpers
// ===========================================================================
__device__ __forceinline__ uint32_t smem_u32(const void* p) {
    uint32_t a;
    asm("{ .reg .u64 t; cvta.to.shared.u64 t, %1; cvt.u32.u64 %0, t; }" : "=r"(a) : "l"(p));
    return a;
}
__device__ __forceinline__ uint32_t swz(uint32_t off) {
    return off ^ ((off >> 3) & 0x70);
}
__device__ __forceinline__ void ldsm4(uint32_t* r, uint32_t addr) {
    asm volatile("ldmatrix.sync.aligned.m8n8.x4.shared.b16 {%0,%1,%2,%3}, [%4];"
                 : "=r"(r[0]), "=r"(r[1]), "=r"(r[2]), "=r"(r[3]) : "r"(addr));
}
__device__ __forceinline__ void ldsm4t(uint32_t* r, uint32_t addr) {
    asm volatile("ldmatrix.sync.aligned.m8n8.x4.trans.shared.b16 {%0,%1,%2,%3}, [%4];"
                 : "=r"(r[0]), "=r"(r[1]), "=r"(r[2]), "=r"(r[3]) : "r"(addr));
}
__device__ __forceinline__ void mma16816(float* c, const uint32_t* a, uint32_t b0, uint32_t b1) {
    asm volatile("mma.sync.aligned.m16n8k16.row.col.f32.f16.f16.f32 "
                 "{%0,%1,%2,%3}, {%4,%5,%6,%7}, {%8,%9}, {%0,%1,%2,%3};"
                 : "+f"(c[0]), "+f"(c[1]), "+f"(c[2]), "+f"(c[3])
                 : "r"(a[0]), "r"(a[1]), "r"(a[2]), "r"(a[3]), "r"(b0), "r"(b1));
}
__device__ __forceinline__ void split2h(float x, float y, uint32_t& hi, uint32_t& lo) {
    __half2 h = __floats2half2_rn(x, y);
    float rx = x - __low2float(h);
    float ry = y - __high2float(h);
    __half2 l = __floats2half2_rn(rx, ry);
    hi = *reinterpret_cast<uint32_t*>(&h);
    lo = *reinterpret_cast<uint32_t*>(&l);
}
__device__ __forceinline__ void split4h(float4 v, uint2& hi, uint2& lo) {
    split2h(v.x, v.y, hi.x, lo.x);
    split2h(v.z, v.w, hi.y, lo.y);
}
__device__ __forceinline__ uint2 pack4h(float4 v) {
    __half2 a = __floats2half2_rn(v.x, v.y);
    __half2 b = __floats2half2_rn(v.z, v.w);
    uint2 r;
    r.x = *reinterpret_cast<uint32_t*>(&a);
    r.y = *reinterpret_cast<uint32_t*>(&b);
    return r;
}
__device__ __forceinline__ uint32_t pack2h(float x, float y) {
    __half2 h = __floats2half2_rn(x, y);
    return *reinterpret_cast<uint32_t*>(&h);
}
__device__ __forceinline__ void cpa16(uint32_t d, const void* s) {
    asm volatile("cp.async.cg.shared.global [%0], [%1], 16;" :: "r"(d), "l"(s));
}
#define CP_COMMIT() asm volatile("cp.async.commit_group;" ::: "memory")
#define CP_WAIT0()  asm volatile("cp.async.wait_group 0;" ::: "memory")
#define CP_WAIT1()  asm volatile("cp.async.wait_group 1;" ::: "memory")

// ===========================================================================
// Fused converter: blocks [0,512) K-hi, [512,1024) V-hi/lo, [1024,1152) W-hi.
// 8 float4 per thread, loads batched front.
// ===========================================================================
extern "C" __global__ void __launch_bounds__(256)
convert_all(const float* __restrict__ K,
            const float* __restrict__ V,
            const float* __restrict__ W)
{
    const int bid = blockIdx.x;
    const int tid = threadIdx.x;
    float4 v[8];
    if (bid < 512) {
        int i0 = (bid * 256 + tid) * 8;
#pragma unroll
        for (int j = 0; j < 8; j++) v[j] = reinterpret_cast<const float4*>(K)[i0 + j];
#pragma unroll
        for (int j = 0; j < 8; j++)
            reinterpret_cast<uint2*>(g_k_h)[i0 + j] = pack4h(v[j]);
    } else if (bid < 1024) {
        int i0 = ((bid - 512) * 256 + tid) * 8;
#pragma unroll
        for (int j = 0; j < 8; j++) v[j] = reinterpret_cast<const float4*>(V)[i0 + j];
#pragma unroll
        for (int j = 0; j < 8; j++) {
            uint2 hi, lo;
            split4h(v[j], hi, lo);
            reinterpret_cast<uint2*>(g_v_h)[i0 + j] = hi;
            reinterpret_cast<uint2*>(g_v_l)[i0 + j] = lo;
        }
    } else {
        int i0 = ((bid - 1024) * 256 + tid) * 8;
#pragma unroll
        for (int j = 0; j < 8; j++) v[j] = reinterpret_cast<const float4*>(W)[i0 + j];
#pragma unroll
        for (int j = 0; j < 8; j++)
            reinterpret_cast<uint2*>(g_w_h)[i0 + j] = pack4h(v[j]);
    }
}

// ===========================================================================
// Row-0 fix: ctx(q=0) = mean_s V (fully-masked row -> uniform softmax)
// ===========================================================================
extern "C" __global__ void __launch_bounds__(256)
meanv_fix(const float* __restrict__ V)
{
    __shared__ float red[256];
    const int h = blockIdx.x, b = blockIdx.y;
    const int t = threadIdx.x;
    const int d = t & 63;
    const int sc = t >> 6;
    const float* src = V + (size_t)b * SS * DD + h * DQ + d;
    float s = 0.0f;
#pragma unroll 8
    for (int i = sc * 512; i < sc * 512 + 512; i++)
        s += src[(size_t)i * DD];
    red[t] = s;
    __syncthreads();
    if (t < 64) {
        float m = (red[t] + red[t + 64] + red[t + 128] + red[t + 192]) * (1.0f / 2048.0f);
        size_t idx = (size_t)b * SS * DD + h * DQ + d;
        __half hh = __float2half_rn(m);
        g_ctx_h[idx] = hh;
        g_ctx_l[idx] = __float2half_rn(m - __half2float(hh));
    }
}

// ===========================================================================
// Attention smem: Q hi (8 KB) + 2 stages x (KH, VH, VL) (24 KB each) = 56 KB.
// Cross-warp reduce buffer reuses [0, 18 KB) after the main loop.
// ===========================================================================
#define SM_QH   0
#define SM_STG  8192
#define STG_STR 24576
#define SMEM_BYTES 57344
#define RED_STR 35

// ===========================================================================
// Flash attention: fp16 HMMA, pipelined K/V, 8 warps (16 rows x 32 keys).
// QK 1-term (qh*kh, Q frags hoisted), PV 2-term (p*vh + p*vl).
// Grid (32,16,2), 256 threads.
// ===========================================================================
extern "C" __global__ void __launch_bounds__(256, 2)
attn_mma(const float* __restrict__ Q)
{
    extern __shared__ char smc[];
    const uint32_t sb = smem_u32(smc);
    const int tid  = threadIdx.x;
    const int lane = tid & 31;
    const int wid  = tid >> 5;
    const int wr   = wid >> 1;    // row group 0..3
    const int wk   = wid & 1;     // key half 0..1

    const int bx = blockIdx.x;
    const int qt = (bx == 31) ? 0 : (31 - bx);
    const int h  = blockIdx.y;
    const int b  = blockIdx.z;
    const int q0 = qt * BM;

    const float* Qb  = Q + ((size_t)(b * SS + q0)) * DD + h * DQ;
    const size_t kvb = (size_t)b * SS * DD + h * DQ;

    const int nkt = qt + 1;

    auto prefetch = [&](int stage, int k0) {
        const uint32_t stg = sb + SM_STG + stage * STG_STR;
#pragma unroll
        for (int q = 0; q < 2; q++) {
            const int id = q * 256 + tid;     // 0..511
            const int r = id >> 3;
            const int g = id & 7;
            const uint32_t off = swz((uint32_t)(r * 128 + g * 16));
            const size_t srco = kvb + (size_t)(k0 + r) * DD + g * 8;
            cpa16(stg + off,         &g_k_h[srco]);
            cpa16(stg + 8192 + off,  &g_v_h[srco]);
            cpa16(stg + 16384 + off, &g_v_l[srco]);
        }
    };

    prefetch(0, 0);
    CP_COMMIT();

    // ---- Load Q tile (hi only; overlaps stage-0 prefetch) ----
#pragma unroll
    for (int it = 0; it < 4; it++) {
        int idx = it * 256 + tid;
        int r = idx >> 4;
        int g = idx & 15;
        float4 q4 = *reinterpret_cast<const float4*>(Qb + (size_t)r * DD + g * 4);
        uint32_t off = swz((uint32_t)(r * 128 + g * 8));
        *reinterpret_cast<uint2*>(smc + SM_QH + off) = pack4h(q4);
    }
    __syncthreads();

    // ---- Hoist Q fragments (loop-invariant across k-tiles) ----
    uint32_t ah[4][4];
#pragma unroll
    for (int kc = 0; kc < 4; kc++) {
        uint32_t offA = swz((uint32_t)((wr * 16 + (lane & 15)) * 128 +
                                       (kc * 16 + (lane >> 4) * 8) * 2));
        ldsm4(ah[kc], sb + SM_QH + offA);
    }

    float Oa[32];
    float l0 = 0.0f, l1 = 0.0f;
#pragma unroll
    for (int i = 0; i < 32; i++) Oa[i] = 0.0f;

    const int qg0 = q0 + wr * 16 + (lane >> 2);
    const int qg1 = qg0 + 8;

    for (int kt = 0; kt < nkt; kt++) {
        const int k0 = kt * BN;

        if (kt + 1 < nkt) {
            prefetch((kt + 1) & 1, k0 + BN);
            CP_COMMIT();
            CP_WAIT1();
        } else {
            CP_WAIT0();
        }
        __syncthreads();

        const uint32_t stg = sb + SM_STG + (kt & 1) * STG_STR;

        // ---- S(16x32) = Qh Kh^T : 1-term ----
        float sc[16];
#pragma unroll
        for (int i = 0; i < 16; i++) sc[i] = 0.0f;

#pragma unroll
        for (int kc = 0; kc < 4; kc++) {
#pragma unroll
            for (int nt4 = 0; nt4 < 2; nt4++) {
                uint32_t offB = swz((uint32_t)((wk * 32 + nt4 * 16 + (lane & 7) + ((lane >> 4) << 3)) * 128 +
                                               (kc * 16 + ((lane >> 3) & 1) * 8) * 2));
                uint32_t bh[4];
                ldsm4(bh, stg + offB);
                mma16816(&sc[nt4 * 8],     ah[kc], bh[0], bh[1]);
                mma16816(&sc[nt4 * 8 + 4], ah[kc], bh[2], bh[3]);
            }
        }

        // ---- softmax (masked -> 0 exactly); single-fp16 P ----
        uint32_t pf[8];
#pragma unroll
        for (int nt = 0; nt < 4; nt++) {
            const int kg = k0 + wk * 32 + nt * 8 + 2 * (lane & 3);
            float p0 = (kg     >= qg0) ? 0.0f : __expf(sc[nt * 4 + 0] * 0.125f);
            float p1 = (kg + 1 >= qg0) ? 0.0f : __expf(sc[nt * 4 + 1] * 0.125f);
            float p2 = (kg     >= qg1) ? 0.0f : __expf(sc[nt * 4 + 2] * 0.125f);
            float p3 = (kg + 1 >= qg1) ? 0.0f : __expf(sc[nt * 4 + 3] * 0.125f);
            l0 += p0 + p1;
            l1 += p2 + p3;
            pf[nt * 2 + 0] = pack2h(p0, p1);
            pf[nt * 2 + 1] = pack2h(p2, p3);
        }

        // ---- O(partial over key-half) += P V : 2-term ----
#pragma unroll
        for (int c = 0; c < 2; c++) {
            const uint32_t* pa = &pf[c * 4];
#pragma unroll
            for (int d4 = 0; d4 < 4; d4++) {
                uint32_t offV = swz((uint32_t)((wk * 32 + c * 16 + (lane & 7) + ((lane >> 3) & 1) * 8) * 128 +
                                               (d4 * 16 + (lane >> 4) * 8) * 2));
                uint32_t bh[4], bl[4];
                ldsm4t(bh, stg + 8192 + offV);
                ldsm4t(bl, stg + 16384 + offV);
                float* o0 = &Oa[d4 * 8];
                float* o1 = &Oa[d4 * 8 + 4];
                mma16816(o0, pa, bh[0], bh[1]);
                mma16816(o1, pa, bh[2], bh[3]);
                mma16816(o0, pa, bl[0], bl[1]);
                mma16816(o1, pa, bl[2], bl[3]);
            }
        }
        __syncthreads();
    }

    // ---- Cross-warp (key-half) reduction via smem ----
    float* sred = reinterpret_cast<float*>(smc);   // [4][32][RED_STR]
    float* slot = sred + (wr * 32 + lane) * RED_STR;
    if (wk == 1) {
#pragma unroll
        for (int i = 0; i < 32; i++) slot[i] = Oa[i];
        slot[32] = l0;
        slot[33] = l1;
    }
    __syncthreads();
    if (wk == 0) {
#pragma unroll
        for (int i = 0; i < 32; i++) Oa[i] += slot[i];
        l0 += slot[32];
        l1 += slot[33];

        l0 += __shfl_xor_sync(0xffffffffu, l0, 1);
        l0 += __shfl_xor_sync(0xffffffffu, l0, 2);
        l1 += __shfl_xor_sync(0xffffffffu, l1, 1);
        l1 += __shfl_xor_sync(0xffffffffu, l1, 2);
        const float inv0 = (l0 > 0.0f) ? 1.0f / l0 : 0.0f;   // row 0 overwritten by meanv_fix
        const float inv1 = 1.0f / l1;

        const int row0 = q0 + wr * 16 + (lane >> 2);
        const size_t base0 = ((size_t)(b * SS + row0)) * DD + h * DQ;
        const size_t base1 = base0 + (size_t)8 * DD;
#pragma unroll
        for (int nt = 0; nt < 8; nt++) {
            const int col = nt * 8 + 2 * (lane & 3);
            uint32_t hi, lo;
            split2h(Oa[nt * 4 + 0] * inv0, Oa[nt * 4 + 1] * inv0, hi, lo);
            *reinterpret_cast<uint32_t*>(&g_ctx_h[base0 + col]) = hi;
            *reinterpret_cast<uint32_t*>(&g_ctx_l[base0 + col]) = lo;
            split2h(Oa[nt * 4 + 2] * inv1, Oa[nt * 4 + 3] * inv1, hi, lo);
            *reinterpret_cast<uint32_t*>(&g_ctx_h[base1 + col]) = hi;
            *reinterpret_cast<uint32_t*>(&g_ctx_l[base1 + col]) = lo;
        }
    }
}

// ===========================================================================
// Projection (unchanged): fp16 2-term, CTA 128x64, BK=32, 256 thr.
// ===========================================================================
#define PNIT (DD / 32)

extern "C" __global__ void __launch_bounds__(256, 2)
proj_mma2(const float* __restrict__ bias,
          float* __restrict__ out)
{
    __shared__ __align__(16) char sA[2][16384];
    __shared__ __align__(16) char sB[2][8192];

    const int tid  = threadIdx.x;
    const int lane = tid & 31;
    const int wid  = tid >> 5;
    const int wm   = wid >> 1;
    const int wn   = wid & 1;
    const int j0   = blockIdx.x * 64;
    const int i0   = blockIdx.y * 128;

    const uint32_t sa0 = smem_u32(sA[0]);
    const uint32_t sa1 = smem_u32(sA[1]);
    const uint32_t sb0 = smem_u32(sB[0]);
    const uint32_t sb1 = smem_u32(sB[1]);

    float acc[32];
#pragma unroll
    for (int i = 0; i < 32; i++) acc[i] = 0.0f;

    auto issue = [&](int stage, int k0) {
        const uint32_t sa = stage ? sa1 : sa0;
        const uint32_t sbm = stage ? sb1 : sb0;
#pragma unroll
        for (int q = 0; q < 4; q++) {
            int id = q * 256 + tid;
            int r = id >> 3;
            int g = id & 7;
            const __half* src = (g < 4)
                ? &g_ctx_h[(size_t)(i0 + r) * DD + k0 + g * 8]
                : &g_ctx_l[(size_t)(i0 + r) * DD + k0 + (g - 4) * 8];
            cpa16(sa + swz((uint32_t)(r * 128 + g * 16)), src);
        }
        {
            int r = tid >> 2;
            int g = tid & 3;
            cpa16(sbm + swz((uint32_t)(r * 128 + g * 16)),
                  &g_w_h[(size_t)(j0 + r) * DD + k0 + g * 8]);
        }
    };

    issue(0, 0);  CP_COMMIT();
    issue(1, 32); CP_COMMIT();

    for (int it = 0; it < PNIT; it++) {
        CP_WAIT1();
        __syncthreads();
        const uint32_t sa = (it & 1) ? sa1 : sa0;
        const uint32_t sbm = (it & 1) ? sb1 : sb0;

#pragma unroll
        for (int kc = 0; kc < 2; kc++) {
            const int kk = kc * 16;
            uint32_t ah[2][4], al[2][4];
#pragma unroll
            for (int m = 0; m < 2; m++) {
                const uint32_t row = wm * 32 + m * 16 + (lane & 15);
                const uint32_t colb = (kk + (lane >> 4) * 8) * 2;
                ldsm4(ah[m], sa + swz(row * 128 + colb));
                ldsm4(al[m], sa + swz(row * 128 + 64 + colb));
            }
            uint32_t bh[2][4];
#pragma unroll
            for (int nt = 0; nt < 2; nt++) {
                const uint32_t rowb = wn * 32 + nt * 16 + (lane & 7) + ((lane >> 4) << 3);
                const uint32_t colb = (kk + ((lane >> 3) & 1) * 8) * 2;
                ldsm4(bh[nt], sbm + swz(rowb * 128 + colb));
            }
#pragma unroll
            for (int m = 0; m < 2; m++)
#pragma unroll
                for (int nt = 0; nt < 2; nt++) {
                    float* c0 = &acc[(m * 2 + nt) * 8];
                    float* c1 = c0 + 4;
                    mma16816(c0, ah[m], bh[nt][0], bh[nt][1]);
                    mma16816(c1, ah[m], bh[nt][2], bh[nt][3]);
                    mma16816(c0, al[m], bh[nt][0], bh[nt][1]);
                    mma16816(c1, al[m], bh[nt][2], bh[nt][3]);
                }
        }

        __syncthreads();
        if (it + 2 < PNIT) {
            issue(it & 1, (it + 2) * 32);
        }
        CP_COMMIT();
    }

#pragma unroll
    for (int m = 0; m < 2; m++) {
        const int row = i0 + wm * 32 + m * 16 + (lane >> 2);
        float* d0 = out + (size_t)row * DD;
        float* d1 = d0 + (size_t)8 * DD;
#pragma unroll
        for (int nt = 0; nt < 2; nt++) {
#pragma unroll
            for (int n8 = 0; n8 < 2; n8++) {
                const int col = j0 + wn * 32 + nt * 16 + n8 * 8 + 2 * (lane & 3);
                const float* c = &acc[(m * 2 + nt) * 8 + n8 * 4];
                const float b0 = bias[col];
                const float b1 = bias[col + 1];
                *reinterpret_cast<float2*>(d0 + col) = make_float2(c[0] + b0, c[1] + b1);
                *reinterpret_cast<float2*>(d1 + col) = make_float2(c[2] + b0, c[3] + b1);
            }
        }
    }
}

// ===========================================================================
extern "C" void kernel_launch(void* const* d_in, const int* in_sizes, int n_in,
                              void* d_out, int out_size)
{
    const float* Q    = (const float*)d_in[0];
    const float* K    = (const float*)d_in[1];
    const float* V    = (const float*)d_in[2];
    const float* Wo_w = (const float*)d_in[3];
    const float* Wo_b = (const float*)d_in[4];

    convert_all<<<1152, 256>>>(K, V, Wo_w);

    cudaFuncSetAttribute(attn_mma, cudaFuncAttributeMaxDynamicSharedMemorySize, SMEM_BYTES);
    dim3 agrid(SS / BM, HH, BB);          // (32, 16, 2)
    attn_mma<<<agrid, 256, SMEM_BYTES>>>(Q);

    dim3 mgrid(HH, BB);
    meanv_fix<<<mgrid, 256>>>(V);

    dim3 pgrid(DD / 64, (BB * SS) / 128); // (16, 32)
    proj_mma2<<<pgrid, 256>>>(Wo_b, (float*)d_out);
}

// round 12
// speedup vs baseline: 2.9535x; 1.4072x over previous
#include <cuda_runtime.h>
#include <cuda_fp16.h>
#include <math.h>
#include <stdint.h>

// Problem constants
#define BB 2
#define SS 2048
#define DD 1024
#define HH 16
#define DQ 64

// Attention tiling
#define BM 64
#define BN 64

// ctx scratch (single fp16)
__device__ __half g_ctx_h[BB * SS * DD];
// W hi fp16
__device__ __half g_w_h[DD * DD];
// K hi; V hi (single fp16 each)
__device__ __half g_k_h[BB * SS * DD];
__device__ __half g_v_h[BB * SS * DD];

// ===========================================================================
// Helpers
// ===========================================================================
__device__ __forceinline__ uint32_t smem_u32(const void* p) {
    uint32_t a;
    asm("{ .reg .u64 t; cvta.to.shared.u64 t, %1; cvt.u32.u64 %0, t; }" : "=r"(a) : "l"(p));
    return a;
}
__device__ __forceinline__ uint32_t swz(uint32_t off) {
    return off ^ ((off >> 3) & 0x70);
}
__device__ __forceinline__ void ldsm4(uint32_t* r, uint32_t addr) {
    asm volatile("ldmatrix.sync.aligned.m8n8.x4.shared.b16 {%0,%1,%2,%3}, [%4];"
                 : "=r"(r[0]), "=r"(r[1]), "=r"(r[2]), "=r"(r[3]) : "r"(addr));
}
__device__ __forceinline__ void ldsm4t(uint32_t* r, uint32_t addr) {
    asm volatile("ldmatrix.sync.aligned.m8n8.x4.trans.shared.b16 {%0,%1,%2,%3}, [%4];"
                 : "=r"(r[0]), "=r"(r[1]), "=r"(r[2]), "=r"(r[3]) : "r"(addr));
}
__device__ __forceinline__ void mma16816(float* c, const uint32_t* a, uint32_t b0, uint32_t b1) {
    asm volatile("mma.sync.aligned.m16n8k16.row.col.f32.f16.f16.f32 "
                 "{%0,%1,%2,%3}, {%4,%5,%6,%7}, {%8,%9}, {%0,%1,%2,%3};"
                 : "+f"(c[0]), "+f"(c[1]), "+f"(c[2]), "+f"(c[3])
                 : "r"(a[0]), "r"(a[1]), "r"(a[2]), "r"(a[3]), "r"(b0), "r"(b1));
}
__device__ __forceinline__ uint2 pack4h(float4 v) {
    __half2 a = __floats2half2_rn(v.x, v.y);
    __half2 b = __floats2half2_rn(v.z, v.w);
    uint2 r;
    r.x = *reinterpret_cast<uint32_t*>(&a);
    r.y = *reinterpret_cast<uint32_t*>(&b);
    return r;
}
__device__ __forceinline__ uint32_t pack2h(float x, float y) {
    __half2 h = __floats2half2_rn(x, y);
    return *reinterpret_cast<uint32_t*>(&h);
}
__device__ __forceinline__ void cpa16(uint32_t d, const void* s) {
    asm volatile("cp.async.cg.shared.global [%0], [%1], 16;" :: "r"(d), "l"(s));
}
#define CP_COMMIT() asm volatile("cp.async.commit_group;" ::: "memory")
#define CP_WAIT0()  asm volatile("cp.async.wait_group 0;" ::: "memory")
#define CP_WAIT1()  asm volatile("cp.async.wait_group 1;" ::: "memory")

// ===========================================================================
// Fused converter: blocks [0,512) K-hi, [512,1024) V-hi, [1024,1152) W-hi.
// ===========================================================================
extern "C" __global__ void __launch_bounds__(256)
convert_all(const float* __restrict__ K,
            const float* __restrict__ V,
            const float* __restrict__ W)
{
    const int bid = blockIdx.x;
    const int tid = threadIdx.x;
    float4 v[8];
    if (bid < 512) {
        int i0 = (bid * 256 + tid) * 8;
#pragma unroll
        for (int j = 0; j < 8; j++) v[j] = reinterpret_cast<const float4*>(K)[i0 + j];
#pragma unroll
        for (int j = 0; j < 8; j++)
            reinterpret_cast<uint2*>(g_k_h)[i0 + j] = pack4h(v[j]);
    } else if (bid < 1024) {
        int i0 = ((bid - 512) * 256 + tid) * 8;
#pragma unroll
        for (int j = 0; j < 8; j++) v[j] = reinterpret_cast<const float4*>(V)[i0 + j];
#pragma unroll
        for (int j = 0; j < 8; j++)
            reinterpret_cast<uint2*>(g_v_h)[i0 + j] = pack4h(v[j]);
    } else {
        int i0 = ((bid - 1024) * 256 + tid) * 8;
#pragma unroll
        for (int j = 0; j < 8; j++) v[j] = reinterpret_cast<const float4*>(W)[i0 + j];
#pragma unroll
        for (int j = 0; j < 8; j++)
            reinterpret_cast<uint2*>(g_w_h)[i0 + j] = pack4h(v[j]);
    }
}

// ===========================================================================
// Row-0 fix: ctx(q=0) = mean_s V (fully-masked row -> uniform softmax)
// ===========================================================================
extern "C" __global__ void __launch_bounds__(256)
meanv_fix(const float* __restrict__ V)
{
    __shared__ float red[256];
    const int h = blockIdx.x, b = blockIdx.y;
    const int t = threadIdx.x;
    const int d = t & 63;
    const int sc = t >> 6;
    const float* src = V + (size_t)b * SS * DD + h * DQ + d;
    float s = 0.0f;
#pragma unroll 8
    for (int i = sc * 512; i < sc * 512 + 512; i++)
        s += src[(size_t)i * DD];
    red[t] = s;
    __syncthreads();
    if (t < 64) {
        float m = (red[t] + red[t + 64] + red[t + 128] + red[t + 192]) * (1.0f / 2048.0f);
        g_ctx_h[(size_t)b * SS * DD + h * DQ + d] = __float2half_rn(m);
    }
}

// ===========================================================================
// Attention smem: Q hi (8 KB) + 2 stages x (KH, VH) (16 KB each) = 40 KB.
// Cross-warp reduce buffer reuses [0, ~18 KB) after the main loop.
// ===========================================================================
#define SM_QH   0
#define SM_STG  8192
#define STG_STR 16384
#define SMEM_BYTES 40960
#define RED_STR 35

// ===========================================================================
// Flash attention: fp16 HMMA, pipelined K/V, 8 warps (16 rows x 32 keys).
// QK 1-term (qh*kh, Q frags hoisted), PV 1-term (p*vh).
// Grid (32,16,2), 256 threads.
// ===========================================================================
extern "C" __global__ void __launch_bounds__(256, 2)
attn_mma(const float* __restrict__ Q)
{
    extern __shared__ char smc[];
    const uint32_t sb = smem_u32(smc);
    const int tid  = threadIdx.x;
    const int lane = tid & 31;
    const int wid  = tid >> 5;
    const int wr   = wid >> 1;    // row group 0..3
    const int wk   = wid & 1;     // key half 0..1

    const int bx = blockIdx.x;
    const int qt = (bx == 31) ? 0 : (31 - bx);
    const int h  = blockIdx.y;
    const int b  = blockIdx.z;
    const int q0 = qt * BM;

    const float* Qb  = Q + ((size_t)(b * SS + q0)) * DD + h * DQ;
    const size_t kvb = (size_t)b * SS * DD + h * DQ;

    const int nkt = qt + 1;

    auto prefetch = [&](int stage, int k0) {
        const uint32_t stg = sb + SM_STG + stage * STG_STR;
#pragma unroll
        for (int q = 0; q < 2; q++) {
            const int id = q * 256 + tid;     // 0..511
            const int r = id >> 3;
            const int g = id & 7;
            const uint32_t off = swz((uint32_t)(r * 128 + g * 16));
            const size_t srco = kvb + (size_t)(k0 + r) * DD + g * 8;
            cpa16(stg + off,        &g_k_h[srco]);
            cpa16(stg + 8192 + off, &g_v_h[srco]);
        }
    };

    prefetch(0, 0);
    CP_COMMIT();

    // ---- Load Q tile (hi only; overlaps stage-0 prefetch) ----
#pragma unroll
    for (int it = 0; it < 4; it++) {
        int idx = it * 256 + tid;
        int r = idx >> 4;
        int g = idx & 15;
        float4 q4 = *reinterpret_cast<const float4*>(Qb + (size_t)r * DD + g * 4);
        uint32_t off = swz((uint32_t)(r * 128 + g * 8));
        *reinterpret_cast<uint2*>(smc + SM_QH + off) = pack4h(q4);
    }
    __syncthreads();

    // ---- Hoist Q fragments (loop-invariant across k-tiles) ----
    uint32_t ah[4][4];
#pragma unroll
    for (int kc = 0; kc < 4; kc++) {
        uint32_t offA = swz((uint32_t)((wr * 16 + (lane & 15)) * 128 +
                                       (kc * 16 + (lane >> 4) * 8) * 2));
        ldsm4(ah[kc], sb + SM_QH + offA);
    }

    float Oa[32];
    float l0 = 0.0f, l1 = 0.0f;
#pragma unroll
    for (int i = 0; i < 32; i++) Oa[i] = 0.0f;

    const int qg0 = q0 + wr * 16 + (lane >> 2);
    const int qg1 = qg0 + 8;

    for (int kt = 0; kt < nkt; kt++) {
        const int k0 = kt * BN;

        if (kt + 1 < nkt) {
            prefetch((kt + 1) & 1, k0 + BN);
            CP_COMMIT();
            CP_WAIT1();
        } else {
            CP_WAIT0();
        }
        __syncthreads();

        const uint32_t stg = sb + SM_STG + (kt & 1) * STG_STR;

        // ---- S(16x32) = Qh Kh^T : 1-term ----
        float sc[16];
#pragma unroll
        for (int i = 0; i < 16; i++) sc[i] = 0.0f;

#pragma unroll
        for (int kc = 0; kc < 4; kc++) {
#pragma unroll
            for (int nt4 = 0; nt4 < 2; nt4++) {
                uint32_t offB = swz((uint32_t)((wk * 32 + nt4 * 16 + (lane & 7) + ((lane >> 4) << 3)) * 128 +
                                               (kc * 16 + ((lane >> 3) & 1) * 8) * 2));
                uint32_t bh[4];
                ldsm4(bh, stg + offB);
                mma16816(&sc[nt4 * 8],     ah[kc], bh[0], bh[1]);
                mma16816(&sc[nt4 * 8 + 4], ah[kc], bh[2], bh[3]);
            }
        }

        // ---- softmax (masked -> 0 exactly); single-fp16 P ----
        uint32_t pf[8];
#pragma unroll
        for (int nt = 0; nt < 4; nt++) {
            const int kg = k0 + wk * 32 + nt * 8 + 2 * (lane & 3);
            float p0 = (kg     >= qg0) ? 0.0f : __expf(sc[nt * 4 + 0] * 0.125f);
            float p1 = (kg + 1 >= qg0) ? 0.0f : __expf(sc[nt * 4 + 1] * 0.125f);
            float p2 = (kg     >= qg1) ? 0.0f : __expf(sc[nt * 4 + 2] * 0.125f);
            float p3 = (kg + 1 >= qg1) ? 0.0f : __expf(sc[nt * 4 + 3] * 0.125f);
            l0 += p0 + p1;
            l1 += p2 + p3;
            pf[nt * 2 + 0] = pack2h(p0, p1);
            pf[nt * 2 + 1] = pack2h(p2, p3);
        }

        // ---- O(partial over key-half) += P V : 1-term ----
#pragma unroll
        for (int c = 0; c < 2; c++) {
            const uint32_t* pa = &pf[c * 4];
#pragma unroll
            for (int d4 = 0; d4 < 4; d4++) {
                uint32_t offV = swz((uint32_t)((wk * 32 + c * 16 + (lane & 7) + ((lane >> 3) & 1) * 8) * 128 +
                                               (d4 * 16 + (lane >> 4) * 8) * 2));
                uint32_t bh[4];
                ldsm4t(bh, stg + 8192 + offV);
                mma16816(&Oa[d4 * 8],     pa, bh[0], bh[1]);
                mma16816(&Oa[d4 * 8 + 4], pa, bh[2], bh[3]);
            }
        }
        __syncthreads();
    }

    // ---- Cross-warp (key-half) reduction via smem ----
    float* sred = reinterpret_cast<float*>(smc);   // [4][32][RED_STR]
    float* slot = sred + (wr * 32 + lane) * RED_STR;
    if (wk == 1) {
#pragma unroll
        for (int i = 0; i < 32; i++) slot[i] = Oa[i];
        slot[32] = l0;
        slot[33] = l1;
    }
    __syncthreads();
    if (wk == 0) {
#pragma unroll
        for (int i = 0; i < 32; i++) Oa[i] += slot[i];
        l0 += slot[32];
        l1 += slot[33];

        l0 += __shfl_xor_sync(0xffffffffu, l0, 1);
        l0 += __shfl_xor_sync(0xffffffffu, l0, 2);
        l1 += __shfl_xor_sync(0xffffffffu, l1, 1);
        l1 += __shfl_xor_sync(0xffffffffu, l1, 2);
        const float inv0 = (l0 > 0.0f) ? 1.0f / l0 : 0.0f;   // row 0 overwritten by meanv_fix
        const float inv1 = 1.0f / l1;

        const int row0 = q0 + wr * 16 + (lane >> 2);
        const size_t base0 = ((size_t)(b * SS + row0)) * DD + h * DQ;
        const size_t base1 = base0 + (size_t)8 * DD;
#pragma unroll
        for (int nt = 0; nt < 8; nt++) {
            const int col = nt * 8 + 2 * (lane & 3);
            *reinterpret_cast<uint32_t*>(&g_ctx_h[base0 + col]) =
                pack2h(Oa[nt * 4 + 0] * inv0, Oa[nt * 4 + 1] * inv0);
            *reinterpret_cast<uint32_t*>(&g_ctx_h[base1 + col]) =
                pack2h(Oa[nt * 4 + 2] * inv1, Oa[nt * 4 + 3] * inv1);
        }
    }
}

// ===========================================================================
// Projection: 1-term fp16 GEMM, CTA 128x64, BK=64, 256 threads, cp.async
// double-buffer. Rows 128 B = 64 fp16 k-values. Grid (16, 32).
// ===========================================================================
#define PNIT (DD / 64)   // 16 k-iterations

extern "C" __global__ void __launch_bounds__(256, 2)
proj_mma2(const float* __restrict__ bias,
          float* __restrict__ out)
{
    __shared__ __align__(16) char sA[2][16384];   // 128 rows x 128 B
    __shared__ __align__(16) char sB[2][8192];    // 64 rows x 128 B

    const int tid  = threadIdx.x;
    const int lane = tid & 31;
    const int wid  = tid >> 5;
    const int wm   = wid >> 1;
    const int wn   = wid & 1;
    const int j0   = blockIdx.x * 64;
    const int i0   = blockIdx.y * 128;

    const uint32_t sa0 = smem_u32(sA[0]);
    const uint32_t sa1 = smem_u32(sA[1]);
    const uint32_t sb0 = smem_u32(sB[0]);
    const uint32_t sb1 = smem_u32(sB[1]);

    float acc[32];
#pragma unroll
    for (int i = 0; i < 32; i++) acc[i] = 0.0f;

    auto issue = [&](int stage, int k0) {
        const uint32_t sa = stage ? sa1 : sa0;
        const uint32_t sbm = stage ? sb1 : sb0;
#pragma unroll
        for (int q = 0; q < 4; q++) {           // A: 1024 16-B chunks
            int id = q * 256 + tid;
            int r = id >> 3;                    // 0..127
            int g = id & 7;
            cpa16(sa + swz((uint32_t)(r * 128 + g * 16)),
                  &g_ctx_h[(size_t)(i0 + r) * DD + k0 + g * 8]);
        }
#pragma unroll
        for (int q = 0; q < 2; q++) {           // B: 512 chunks
            int id = q * 256 + tid;
            int r = id >> 3;                    // 0..63
            int g = id & 7;
            cpa16(sbm + swz((uint32_t)(r * 128 + g * 16)),
                  &g_w_h[(size_t)(j0 + r) * DD + k0 + g * 8]);
        }
    };

    issue(0, 0);  CP_COMMIT();
    issue(1, 64); CP_COMMIT();

    for (int it = 0; it < PNIT; it++) {
        CP_WAIT1();
        __syncthreads();
        const uint32_t sa = (it & 1) ? sa1 : sa0;
        const uint32_t sbm = (it & 1) ? sb1 : sb0;

#pragma unroll
        for (int kc = 0; kc < 4; kc++) {
            uint32_t ah[2][4];
#pragma unroll
            for (int m = 0; m < 2; m++) {
                const uint32_t row = wm * 32 + m * 16 + (lane & 15);
                const uint32_t colb = (kc * 16 + (lane >> 4) * 8) * 2;
                ldsm4(ah[m], sa + swz(row * 128 + colb));
            }
            uint32_t bh[2][4];
#pragma unroll
            for (int nt = 0; nt < 2; nt++) {
                const uint32_t rowb = wn * 32 + nt * 16 + (lane & 7) + ((lane >> 4) << 3);
                const uint32_t colb = (kc * 16 + ((lane >> 3) & 1) * 8) * 2;
                ldsm4(bh[nt], sbm + swz(rowb * 128 + colb));
            }
#pragma unroll
            for (int m = 0; m < 2; m++)
#pragma unroll
                for (int nt = 0; nt < 2; nt++) {
                    float* c0 = &acc[(m * 2 + nt) * 8];
                    float* c1 = c0 + 4;
                    mma16816(c0, ah[m], bh[nt][0], bh[nt][1]);
                    mma16816(c1, ah[m], bh[nt][2], bh[nt][3]);
                }
        }

        __syncthreads();
        if (it + 2 < PNIT) {
            issue(it & 1, (it + 2) * 64);
        }
        CP_COMMIT();
    }

    // ---- Epilogue: + bias, f32 out ----
#pragma unroll
    for (int m = 0; m < 2; m++) {
        const int row = i0 + wm * 32 + m * 16 + (lane >> 2);
        float* d0 = out + (size_t)row * DD;
        float* d1 = d0 + (size_t)8 * DD;
#pragma unroll
        for (int nt = 0; nt < 2; nt++) {
#pragma unroll
            for (int n8 = 0; n8 < 2; n8++) {
                const int col = j0 + wn * 32 + nt * 16 + n8 * 8 + 2 * (lane & 3);
                const float* c = &acc[(m * 2 + nt) * 8 + n8 * 4];
                const float b0 = bias[col];
                const float b1 = bias[col + 1];
                *reinterpret_cast<float2*>(d0 + col) = make_float2(c[0] + b0, c[1] + b1);
                *reinterpret_cast<float2*>(d1 + col) = make_float2(c[2] + b0, c[3] + b1);
            }
        }
    }
}

// ===========================================================================
extern "C" void kernel_launch(void* const* d_in, const int* in_sizes, int n_in,
                              void* d_out, int out_size)
{
    const float* Q    = (const float*)d_in[0];
    const float* K    = (const float*)d_in[1];
    const float* V    = (const float*)d_in[2];
    const float* Wo_w = (const float*)d_in[3];
    const float* Wo_b = (const float*)d_in[4];

    convert_all<<<1152, 256>>>(K, V, Wo_w);

    cudaFuncSetAttribute(attn_mma, cudaFuncAttributeMaxDynamicSharedMemorySize, SMEM_BYTES);
    dim3 agrid(SS / BM, HH, BB);          // (32, 16, 2)
    attn_mma<<<agrid, 256, SMEM_BYTES>>>(Q);

    dim3 mgrid(HH, BB);
    meanv_fix<<<mgrid, 256>>>(V);

    dim3 pgrid(DD / 64, (BB * SS) / 128); // (16, 32)
    proj_mma2<<<pgrid, 256>>>(Wo_b, (float*)d_out);
}